// round 2
// baseline (speedup 1.0000x reference)
#include <cuda_runtime.h>
#include <cstdint>

#define D_MODEL 768
#define NHEAD   12
#define SEQ     1024
#define BATCH   4
#define NTOK    (BATCH*SEQ)        /* 4096 */
#define DH      (D_MODEL*NHEAD)    /* 9216 */
#define DFF     (4*D_MODEL)        /* 3072 */
#define LN_EPS  1e-5f

// ---------------- scratch (device globals; no allocation allowed) ----------------
__device__ float g_Y  [(size_t)NTOK * D_MODEL];               // LN output (reused)
__device__ float g_Q  [(size_t)NTOK * DH];
__device__ float g_K  [(size_t)NTOK * DH];
__device__ float g_V  [(size_t)NTOK * DH];
__device__ float g_S  [(size_t)BATCH * NHEAD * SEQ * SEQ];    // attention scores
__device__ float g_ATT[(size_t)NTOK * DH];
__device__ float g_X1 [(size_t)NTOK * D_MODEL];               // post-attention residual
__device__ float g_H1 [(size_t)NTOK * DFF];                   // MLP hidden

// ---------------- helpers ----------------
__device__ __forceinline__ float to_tf32(float x) {
    uint32_t u;
    asm("cvt.rna.tf32.f32 %0, %1;" : "=r"(u) : "f"(x));
    return __uint_as_float(u);
}

__device__ __forceinline__ void mma_tf32(float c[4],
                                         uint32_t a0, uint32_t a1, uint32_t a2, uint32_t a3,
                                         uint32_t b0, uint32_t b1) {
    asm("mma.sync.aligned.m16n8k8.row.col.f32.tf32.tf32.f32 "
        "{%0,%1,%2,%3}, {%4,%5,%6,%7}, {%8,%9}, {%0,%1,%2,%3};"
        : "+f"(c[0]), "+f"(c[1]), "+f"(c[2]), "+f"(c[3])
        : "r"(a0), "r"(a1), "r"(a2), "r"(a3), "r"(b0), "r"(b1));
}

// ---------------- generic tf32 tensor-core GEMM ----------------
// C[m,n] = epilogue( alpha * sum_k A[m,k] * B(k,n) )
//   BT=false: B is K x N row-major (element (k,n) at B[k*ldb + n])
//   BT=true : B is N x K row-major (element (k,n) at B[n*ldb + k])  -> A @ B^T
// Batched over blockIdx.z with z = zo*innerCnt + zi and per-operand (outer, inner)
// strides, so per-(batch, head) sub-matrices of the packed QKV tensors work.
// All dims assumed divisible: M%128==0, N%128==0, K%32==0 (true for every call site).
template<bool BT, bool RELU, bool HASB, bool HASR>
__global__ __launch_bounds__(256, 2)
void gemm_tf32(const float* __restrict__ A, const float* __restrict__ B,
               const float* __restrict__ bias, const float* __restrict__ Res,
               float* __restrict__ C,
               int K, int lda, int ldb, int ldc, int ldr, float alpha,
               long long saO, long long saI, long long sbO, long long sbI,
               long long scO, long long scI, long long srO, long long srI,
               int innerCnt)
{
    const int z  = blockIdx.z;
    const int zo = z / innerCnt;
    const int zi = z - zo * innerCnt;
    A += zo * saO + zi * saI;
    B += zo * sbO + zi * sbI;
    C += zo * scO + zi * scI;
    if (HASR) Res += zo * srO + zi * srI;

    __shared__ float As[32][132];   // As[k][m], +4 pad
    __shared__ float Bs[32][132];   // Bs[k][n]

    const int tid    = threadIdx.x;
    const int warpId = tid >> 5;
    const int lane   = tid & 31;
    const int wm  = warpId >> 2;    // 0..1  -> 64 rows each
    const int wn  = warpId & 3;     // 0..3  -> 32 cols each
    const int g   = lane >> 2;      // groupID 0..7
    const int tig = lane & 3;       // threadID in group

    const int m0 = blockIdx.y * 128;
    const int n0 = blockIdx.x * 128;

    float acc[4][4][4];
    #pragma unroll
    for (int mt = 0; mt < 4; mt++)
        #pragma unroll
        for (int nt = 0; nt < 4; nt++)
            #pragma unroll
            for (int r = 0; r < 4; r++) acc[mt][nt][r] = 0.f;

    for (int k0 = 0; k0 < K; k0 += 32) {
        // ---- load A tile 128x32, store transposed As[k][m] (tf32-rounded) ----
        #pragma unroll
        for (int j = 0; j < 4; j++) {
            const int row = (tid >> 3) + j * 32;       // 0..127
            const int kk  = (tid & 7) * 4;             // 0..28
            const float4 v = *reinterpret_cast<const float4*>(
                A + (long long)(m0 + row) * lda + k0 + kk);
            As[kk + 0][row] = to_tf32(v.x);
            As[kk + 1][row] = to_tf32(v.y);
            As[kk + 2][row] = to_tf32(v.z);
            As[kk + 3][row] = to_tf32(v.w);
        }
        // ---- load B tile -> Bs[k][n] ----
        if (!BT) {
            #pragma unroll
            for (int j = 0; j < 4; j++) {
                const int row = (tid >> 5) + j * 8;    // k: 0..31
                const int nv  = (tid & 31) * 4;        // n: 0..124
                const float4 v = *reinterpret_cast<const float4*>(
                    B + (long long)(k0 + row) * ldb + n0 + nv);
                Bs[row][nv + 0] = to_tf32(v.x);
                Bs[row][nv + 1] = to_tf32(v.y);
                Bs[row][nv + 2] = to_tf32(v.z);
                Bs[row][nv + 3] = to_tf32(v.w);
            }
        } else {
            #pragma unroll
            for (int j = 0; j < 4; j++) {
                const int row = (tid >> 3) + j * 32;   // n: 0..127
                const int kk  = (tid & 7) * 4;
                const float4 v = *reinterpret_cast<const float4*>(
                    B + (long long)(n0 + row) * ldb + k0 + kk);
                Bs[kk + 0][row] = to_tf32(v.x);
                Bs[kk + 1][row] = to_tf32(v.y);
                Bs[kk + 2][row] = to_tf32(v.z);
                Bs[kk + 3][row] = to_tf32(v.w);
            }
        }
        __syncthreads();

        // ---- 4 x k8 mma steps ----
        #pragma unroll
        for (int ks = 0; ks < 32; ks += 8) {
            uint32_t af[4][4], bf[4][2];
            #pragma unroll
            for (int mt = 0; mt < 4; mt++) {
                const int mr = wm * 64 + mt * 16 + g;
                af[mt][0] = __float_as_uint(As[ks + tig    ][mr]);
                af[mt][1] = __float_as_uint(As[ks + tig    ][mr + 8]);
                af[mt][2] = __float_as_uint(As[ks + tig + 4][mr]);
                af[mt][3] = __float_as_uint(As[ks + tig + 4][mr + 8]);
            }
            #pragma unroll
            for (int nt = 0; nt < 4; nt++) {
                const int nc = wn * 32 + nt * 8 + g;
                bf[nt][0] = __float_as_uint(Bs[ks + tig    ][nc]);
                bf[nt][1] = __float_as_uint(Bs[ks + tig + 4][nc]);
            }
            #pragma unroll
            for (int mt = 0; mt < 4; mt++)
                #pragma unroll
                for (int nt = 0; nt < 4; nt++)
                    mma_tf32(acc[mt][nt], af[mt][0], af[mt][1], af[mt][2], af[mt][3],
                             bf[nt][0], bf[nt][1]);
        }
        __syncthreads();
    }

    // ---- epilogue ----
    #pragma unroll
    for (int mt = 0; mt < 4; mt++) {
        const int mbase = m0 + wm * 64 + mt * 16 + g;
        #pragma unroll
        for (int nt = 0; nt < 4; nt++) {
            const int n = n0 + wn * 32 + nt * 8 + tig * 2;
            float bv0 = 0.f, bv1 = 0.f;
            if (HASB) { bv0 = bias[n]; bv1 = bias[n + 1]; }
            #pragma unroll
            for (int h = 0; h < 2; h++) {              // h=0: rows g, regs 0/1; h=1: rows g+8, regs 2/3
                const int m = mbase + h * 8;
                float x0 = alpha * acc[mt][nt][h * 2 + 0] + bv0;
                float x1 = alpha * acc[mt][nt][h * 2 + 1] + bv1;
                if (RELU) { x0 = fmaxf(x0, 0.f); x1 = fmaxf(x1, 0.f); }
                if (HASR) {
                    x0 += Res[(long long)m * ldr + n];
                    x1 += Res[(long long)m * ldr + n + 1];
                }
                C[(long long)m * ldc + n]     = x0;
                C[(long long)m * ldc + n + 1] = x1;
            }
        }
    }
}

// ---------------- layernorm: one block per token row (D=768, 256 threads) ----------------
__global__ void layernorm_kernel(const float* __restrict__ x,
                                 const float* __restrict__ gm,
                                 const float* __restrict__ bt,
                                 float* __restrict__ y)
{
    const long long base = (long long)blockIdx.x * D_MODEL;
    const int t = threadIdx.x;
    float v[3];
    float lsum = 0.f, lsq = 0.f;
    #pragma unroll
    for (int i = 0; i < 3; i++) {
        v[i] = x[base + t + i * 256];
        lsum += v[i];
        lsq  += v[i] * v[i];
    }
    __shared__ float sh[16];
    #pragma unroll
    for (int o = 16; o; o >>= 1) {
        lsum += __shfl_xor_sync(0xffffffffu, lsum, o);
        lsq  += __shfl_xor_sync(0xffffffffu, lsq,  o);
    }
    const int wid = t >> 5, lane = t & 31;
    if (lane == 0) { sh[wid] = lsum; sh[8 + wid] = lsq; }
    __syncthreads();
    if (wid == 0) {
        float a = (lane < 8) ? sh[lane] : 0.f;
        float b = (lane < 8) ? sh[8 + lane] : 0.f;
        #pragma unroll
        for (int o = 4; o; o >>= 1) {
            a += __shfl_xor_sync(0xffffffffu, a, o);
            b += __shfl_xor_sync(0xffffffffu, b, o);
        }
        if (lane == 0) { sh[0] = a; sh[1] = b; }
    }
    __syncthreads();
    const float mu   = sh[0] * (1.f / D_MODEL);
    const float var  = sh[1] * (1.f / D_MODEL) - mu * mu;
    const float rstd = rsqrtf(var + LN_EPS);
    #pragma unroll
    for (int i = 0; i < 3; i++) {
        const int idx = t + i * 256;
        y[base + idx] = (v[i] - mu) * rstd * gm[idx] + bt[idx];
    }
}

// ---------------- row softmax over length-1024 rows (one block per row) ----------------
__global__ void softmax_kernel(float* __restrict__ S)
{
    float* p = S + (long long)blockIdx.x * SEQ;
    const int t = threadIdx.x;
    const int wid = t >> 5, lane = t & 31;
    __shared__ float sh[8];

    float v[4];
    float mx = -3.4e38f;
    #pragma unroll
    for (int i = 0; i < 4; i++) { v[i] = p[t + i * 256]; mx = fmaxf(mx, v[i]); }
    #pragma unroll
    for (int o = 16; o; o >>= 1) mx = fmaxf(mx, __shfl_xor_sync(0xffffffffu, mx, o));
    if (lane == 0) sh[wid] = mx;
    __syncthreads();
    if (wid == 0) {
        float a = (lane < 8) ? sh[lane] : -3.4e38f;
        #pragma unroll
        for (int o = 4; o; o >>= 1) a = fmaxf(a, __shfl_xor_sync(0xffffffffu, a, o));
        if (lane == 0) sh[0] = a;
    }
    __syncthreads();
    mx = sh[0];
    __syncthreads();

    float s = 0.f;
    #pragma unroll
    for (int i = 0; i < 4; i++) { v[i] = __expf(v[i] - mx); s += v[i]; }
    #pragma unroll
    for (int o = 16; o; o >>= 1) s += __shfl_xor_sync(0xffffffffu, s, o);
    if (lane == 0) sh[wid] = s;
    __syncthreads();
    if (wid == 0) {
        float a = (lane < 8) ? sh[lane] : 0.f;
        #pragma unroll
        for (int o = 4; o; o >>= 1) a += __shfl_xor_sync(0xffffffffu, a, o);
        if (lane == 0) sh[0] = a;
    }
    __syncthreads();
    const float inv = 1.f / sh[0];
    #pragma unroll
    for (int i = 0; i < 4; i++) p[t + i * 256] = v[i] * inv;
}

// ---------------- launch ----------------
extern "C" void kernel_launch(void* const* d_in, const int* in_sizes, int n_in,
                              void* d_out, int out_size)
{
    const float* x    = (const float*)d_in[0];
    const float* Wq   = (const float*)d_in[1];
    const float* Wk   = (const float*)d_in[2];
    const float* Wv   = (const float*)d_in[3];
    const float* Wu   = (const float*)d_in[4];
    const float* bu   = (const float*)d_in[5];
    const float* ln1g = (const float*)d_in[6];
    const float* ln1b = (const float*)d_in[7];
    const float* ln2g = (const float*)d_in[8];
    const float* ln2b = (const float*)d_in[9];
    const float* W1   = (const float*)d_in[10];
    const float* b1   = (const float*)d_in[11];
    const float* W2   = (const float*)d_in[12];
    const float* b2   = (const float*)d_in[13];
    float* out = (float*)d_out;

    float *Y, *Q, *Kp, *V, *S, *ATT, *X1, *H1;
    cudaGetSymbolAddress((void**)&Y,   g_Y);
    cudaGetSymbolAddress((void**)&Q,   g_Q);
    cudaGetSymbolAddress((void**)&Kp,  g_K);
    cudaGetSymbolAddress((void**)&V,   g_V);
    cudaGetSymbolAddress((void**)&S,   g_S);
    cudaGetSymbolAddress((void**)&ATT, g_ATT);
    cudaGetSymbolAddress((void**)&X1,  g_X1);
    cudaGetSymbolAddress((void**)&H1,  g_H1);

    const float scale = 0.028867513459481287f * 1.25f; // placeholder replaced below
    const float inv_sqrt_d = 0.03608439182435161f;     // 1/sqrt(768)
    (void)scale;

    // 1) LN1: x -> Y
    layernorm_kernel<<<NTOK, 256>>>(x, ln1g, ln1b, Y);

    // 2) Q/K/V = Y @ W{q,k,v}   (M=4096, N=9216, K=768)
    {
        dim3 grid(DH / 128, NTOK / 128, 1);
        gemm_tf32<false,false,false,false><<<grid, 256>>>(Y, Wq, nullptr, nullptr, Q,
            D_MODEL, D_MODEL, DH, DH, 0, 1.f, 0,0,0,0,0,0,0,0, 1);
        gemm_tf32<false,false,false,false><<<grid, 256>>>(Y, Wk, nullptr, nullptr, Kp,
            D_MODEL, D_MODEL, DH, DH, 0, 1.f, 0,0,0,0,0,0,0,0, 1);
        gemm_tf32<false,false,false,false><<<grid, 256>>>(Y, Wv, nullptr, nullptr, V,
            D_MODEL, D_MODEL, DH, DH, 0, 1.f, 0,0,0,0,0,0,0,0, 1);
    }

    // 3) S[b,h] = (Q_bh @ K_bh^T) / sqrt(768)   (M=N=1024, K=768, batch=48)
    {
        dim3 grid(SEQ / 128, SEQ / 128, BATCH * NHEAD);
        gemm_tf32<true,false,false,false><<<grid, 256>>>(Q, Kp, nullptr, nullptr, S,
            D_MODEL, DH, DH, SEQ, 0, inv_sqrt_d,
            (long long)SEQ * DH, (long long)D_MODEL,        // A(Q): per-b, per-h
            (long long)SEQ * DH, (long long)D_MODEL,        // B(K): per-b, per-h
            (long long)NHEAD * SEQ * SEQ, (long long)SEQ * SEQ,
            0, 0, NHEAD);
    }

    // 4) softmax over rows of S
    softmax_kernel<<<BATCH * NHEAD * SEQ, 256>>>(S);

    // 5) ATT[b,:,h,:] = P_bh @ V_bh   (M=1024, N=768, K=1024, batch=48)
    {
        dim3 grid(D_MODEL / 128, SEQ / 128, BATCH * NHEAD);
        gemm_tf32<false,false,false,false><<<grid, 256>>>(S, V, nullptr, nullptr, ATT,
            SEQ, SEQ, DH, DH, 0, 1.f,
            (long long)NHEAD * SEQ * SEQ, (long long)SEQ * SEQ,
            (long long)SEQ * DH, (long long)D_MODEL,
            (long long)SEQ * DH, (long long)D_MODEL,
            0, 0, NHEAD);
    }

    // 6) X1 = ATT @ Wu + bu + x   (M=4096, N=768, K=9216)
    {
        dim3 grid(D_MODEL / 128, NTOK / 128, 1);
        gemm_tf32<false,false,true,true><<<grid, 256>>>(ATT, Wu, bu, x, X1,
            DH, DH, D_MODEL, D_MODEL, D_MODEL, 1.f, 0,0,0,0,0,0,0,0, 1);
    }

    // 7) LN2: X1 -> Y
    layernorm_kernel<<<NTOK, 256>>>(X1, ln2g, ln2b, Y);

    // 8) H1 = relu(Y @ W1 + b1)   (M=4096, N=3072, K=768)
    {
        dim3 grid(DFF / 128, NTOK / 128, 1);
        gemm_tf32<false,true,true,false><<<grid, 256>>>(Y, W1, b1, nullptr, H1,
            D_MODEL, D_MODEL, DFF, DFF, 0, 1.f, 0,0,0,0,0,0,0,0, 1);
    }

    // 9) out = H1 @ W2 + b2 + X1   (M=4096, N=768, K=3072)
    {
        dim3 grid(D_MODEL / 128, NTOK / 128, 1);
        gemm_tf32<false,false,true,true><<<grid, 256>>>(H1, W2, b2, X1, out,
            DFF, DFF, D_MODEL, D_MODEL, D_MODEL, 1.f, 0,0,0,0,0,0,0,0, 1);
    }

    (void)in_sizes; (void)n_in; (void)out_size;
}

// round 3
// speedup vs baseline: 1.2234x; 1.2234x over previous
#include <cuda_runtime.h>
#include <cstdint>

#define D_MODEL 768
#define NHEAD   12
#define SEQ     1024
#define BATCH   4
#define NTOK    (BATCH*SEQ)        /* 4096 */
#define DH      (D_MODEL*NHEAD)    /* 9216 */
#define DFF     (4*D_MODEL)        /* 3072 */
#define LN_EPS  1e-5f

// ---------------- scratch (device globals; no allocation allowed) ----------------
__device__ float g_Y  [(size_t)NTOK * D_MODEL];               // LN output (reused)
__device__ float g_Q  [(size_t)NTOK * DH];
__device__ float g_K  [(size_t)NTOK * DH];
__device__ float g_V  [(size_t)NTOK * DH];
__device__ float g_S  [(size_t)BATCH * NHEAD * SEQ * SEQ];    // attention scores
__device__ float g_ATT[(size_t)NTOK * DH];
__device__ float g_X1 [(size_t)NTOK * D_MODEL];               // post-attention residual
__device__ float g_H1 [(size_t)NTOK * DFF];                   // MLP hidden

// ---------------- helpers ----------------
__device__ __forceinline__ float to_tf32(float x) {
    uint32_t u;
    asm("cvt.rna.tf32.f32 %0, %1;" : "=r"(u) : "f"(x));
    return __uint_as_float(u);
}

__device__ __forceinline__ void mma_tf32(float c[4],
                                         uint32_t a0, uint32_t a1, uint32_t a2, uint32_t a3,
                                         uint32_t b0, uint32_t b1) {
    asm("mma.sync.aligned.m16n8k8.row.col.f32.tf32.tf32.f32 "
        "{%0,%1,%2,%3}, {%4,%5,%6,%7}, {%8,%9}, {%0,%1,%2,%3};"
        : "+f"(c[0]), "+f"(c[1]), "+f"(c[2]), "+f"(c[3])
        : "r"(a0), "r"(a1), "r"(a2), "r"(a3), "r"(b0), "r"(b1));
}

// ---------------- generic tf32 tensor-core GEMM (fragment-smem + reg double-buffer) --
// C[m,n] = epilogue( alpha * sum_k A[m,k] * B(k,n) )
//   BT=false: B is K x N row-major.  BT=true: B is N x K row-major -> A @ B^T.
// Batched via blockIdx.z = zo*innerCnt + zi with per-operand (outer, inner) strides.
// All dims divisible: M%128==0, N%128==0, K%32==0 (true at every call site).
//
// A smem: fragment-major. Element (m,k) of the 128x32 tile lives at
//   tile = (k>>3)*8 + (m>>4);  lane = (m&7)*4 + ((k&3) ^ (k>>3));  r = ((k>>2)&1)*2 + ((m>>3)&1)
//   Asf[tile*128 + lane*4 + r]
// Consumer: one conflict-free LDS.128 per (ks, mtile) delivers regs a0..a3 in order.
// B smem: Bs[k][n], 132-float pitch (vectorizable STS.128 in NN path, low-conflict LDS).
template<bool BT, bool RELU, bool HASB, bool HASR>
__global__ __launch_bounds__(256, 2)
void gemm_tf32(const float* __restrict__ A, const float* __restrict__ B,
               const float* __restrict__ bias, const float* __restrict__ Res,
               float* __restrict__ C,
               int K, int lda, int ldb, int ldc, int ldr, float alpha,
               long long saO, long long saI, long long sbO, long long sbI,
               long long scO, long long scI, long long srO, long long srI,
               int innerCnt)
{
    const int z  = blockIdx.z;
    const int zo = z / innerCnt;
    const int zi = z - zo * innerCnt;
    A += zo * saO + zi * saI;
    B += zo * sbO + zi * sbI;
    C += zo * scO + zi * scI;
    if (HASR) Res += zo * srO + zi * srI;

    __shared__ float Asf[4096];     // 4 ks-tiles x 8 m-tiles x 128 floats (16KB)
    __shared__ float Bs[32][132];   // Bs[k][n], +4 pad (16.9KB)

    const int tid    = threadIdx.x;
    const int warpId = tid >> 5;
    const int lane   = tid & 31;
    const int wm  = warpId >> 2;    // 0..1  -> 64 rows each
    const int wn  = warpId & 3;     // 0..3  -> 32 cols each
    const int g   = lane >> 2;      // groupID 0..7
    const int tig = lane & 3;       // threadID in group

    const int m0 = blockIdx.y * 128;
    const int n0 = blockIdx.x * 128;

    // producer-side decompositions (constant across k-tiles)
    const int aRow = tid >> 3;            // 0..31, + j*32 -> m
    const int aKK  = (tid & 7) * 4;       // 0..28
    const int aKs    = aKK >> 3;          // 0..3
    const int aKhalf = (aKK >> 2) & 1;
    const int bRowNN = tid >> 5;          // + j*8 -> k row (NN path)
    const int bNV    = (tid & 31) * 4;    // n offset (NN path)

    float acc[4][4][4];
    #pragma unroll
    for (int mt = 0; mt < 4; mt++)
        #pragma unroll
        for (int nt = 0; nt < 4; nt++)
            #pragma unroll
            for (int r = 0; r < 4; r++) acc[mt][nt][r] = 0.f;

    float4 aReg[4], bReg[4];

    // ---- global load helpers (into registers) ----
    auto loadA = [&](int k0) {
        #pragma unroll
        for (int j = 0; j < 4; j++)
            aReg[j] = *reinterpret_cast<const float4*>(
                A + (long long)(m0 + aRow + j * 32) * lda + k0 + aKK);
    };
    auto loadB = [&](int k0) {
        if (!BT) {
            #pragma unroll
            for (int j = 0; j < 4; j++)
                bReg[j] = *reinterpret_cast<const float4*>(
                    B + (long long)(k0 + bRowNN + j * 8) * ldb + n0 + bNV);
        } else {
            #pragma unroll
            for (int j = 0; j < 4; j++)
                bReg[j] = *reinterpret_cast<const float4*>(
                    B + (long long)(n0 + aRow + j * 32) * ldb + k0 + aKK);
        }
    };
    // ---- smem store helpers (with tf32 rounding) ----
    auto storeA = [&]() {
        #pragma unroll
        for (int j = 0; j < 4; j++) {
            const int m   = aRow + j * 32;
            const int mtg = m >> 4;
            const int gg  = m & 7;
            const int mhi = (m >> 3) & 1;
            const int r   = aKhalf * 2 + mhi;
            float* base = &Asf[(aKs * 8 + mtg) * 128 + gg * 16 + r];
            base[(0 ^ aKs) * 4] = to_tf32(aReg[j].x);
            base[(1 ^ aKs) * 4] = to_tf32(aReg[j].y);
            base[(2 ^ aKs) * 4] = to_tf32(aReg[j].z);
            base[(3 ^ aKs) * 4] = to_tf32(aReg[j].w);
        }
    };
    auto storeB = [&]() {
        if (!BT) {
            #pragma unroll
            for (int j = 0; j < 4; j++) {
                float4 w;
                w.x = to_tf32(bReg[j].x); w.y = to_tf32(bReg[j].y);
                w.z = to_tf32(bReg[j].z); w.w = to_tf32(bReg[j].w);
                *reinterpret_cast<float4*>(&Bs[bRowNN + j * 8][bNV]) = w;
            }
        } else {
            #pragma unroll
            for (int j = 0; j < 4; j++) {
                const int n = aRow + j * 32;
                Bs[aKK + 0][n] = to_tf32(bReg[j].x);
                Bs[aKK + 1][n] = to_tf32(bReg[j].y);
                Bs[aKK + 2][n] = to_tf32(bReg[j].z);
                Bs[aKK + 3][n] = to_tf32(bReg[j].w);
            }
        }
    };

    loadA(0); loadB(0);

    for (int k0 = 0; k0 < K; k0 += 32) {
        storeA(); storeB();
        __syncthreads();
        if (k0 + 32 < K) { loadA(k0 + 32); loadB(k0 + 32); }  // in-flight during mma

        #pragma unroll
        for (int ksi = 0; ksi < 4; ksi++) {
            const int ks8   = ksi * 8;
            const int lanep = lane ^ ksi;
            float4 af4[4];
            uint32_t bf[4][2];
            #pragma unroll
            for (int mt = 0; mt < 4; mt++)
                af4[mt] = *reinterpret_cast<const float4*>(
                    &Asf[(ksi * 8 + wm * 4 + mt) * 128 + lanep * 4]);
            #pragma unroll
            for (int nt = 0; nt < 4; nt++) {
                const int nc = wn * 32 + nt * 8 + g;
                bf[nt][0] = __float_as_uint(Bs[ks8 + tig    ][nc]);
                bf[nt][1] = __float_as_uint(Bs[ks8 + tig + 4][nc]);
            }
            #pragma unroll
            for (int mt = 0; mt < 4; mt++)
                #pragma unroll
                for (int nt = 0; nt < 4; nt++)
                    mma_tf32(acc[mt][nt],
                             __float_as_uint(af4[mt].x), __float_as_uint(af4[mt].y),
                             __float_as_uint(af4[mt].z), __float_as_uint(af4[mt].w),
                             bf[nt][0], bf[nt][1]);
        }
        __syncthreads();
    }

    // ---- epilogue ----
    #pragma unroll
    for (int mt = 0; mt < 4; mt++) {
        const int mbase = m0 + wm * 64 + mt * 16 + g;
        #pragma unroll
        for (int nt = 0; nt < 4; nt++) {
            const int n = n0 + wn * 32 + nt * 8 + tig * 2;
            float bv0 = 0.f, bv1 = 0.f;
            if (HASB) { bv0 = bias[n]; bv1 = bias[n + 1]; }
            #pragma unroll
            for (int h = 0; h < 2; h++) {
                const int m = mbase + h * 8;
                float x0 = alpha * acc[mt][nt][h * 2 + 0] + bv0;
                float x1 = alpha * acc[mt][nt][h * 2 + 1] + bv1;
                if (RELU) { x0 = fmaxf(x0, 0.f); x1 = fmaxf(x1, 0.f); }
                if (HASR) {
                    x0 += Res[(long long)m * ldr + n];
                    x1 += Res[(long long)m * ldr + n + 1];
                }
                C[(long long)m * ldc + n]     = x0;
                C[(long long)m * ldc + n + 1] = x1;
            }
        }
    }
}

// ---------------- layernorm: one block per token row (D=768, 256 threads) ----------------
__global__ void layernorm_kernel(const float* __restrict__ x,
                                 const float* __restrict__ gm,
                                 const float* __restrict__ bt,
                                 float* __restrict__ y)
{
    const long long base = (long long)blockIdx.x * D_MODEL;
    const int t = threadIdx.x;
    float v[3];
    float lsum = 0.f, lsq = 0.f;
    #pragma unroll
    for (int i = 0; i < 3; i++) {
        v[i] = x[base + t + i * 256];
        lsum += v[i];
        lsq  += v[i] * v[i];
    }
    __shared__ float sh[16];
    #pragma unroll
    for (int o = 16; o; o >>= 1) {
        lsum += __shfl_xor_sync(0xffffffffu, lsum, o);
        lsq  += __shfl_xor_sync(0xffffffffu, lsq,  o);
    }
    const int wid = t >> 5, lane = t & 31;
    if (lane == 0) { sh[wid] = lsum; sh[8 + wid] = lsq; }
    __syncthreads();
    if (wid == 0) {
        float a = (lane < 8) ? sh[lane] : 0.f;
        float b = (lane < 8) ? sh[8 + lane] : 0.f;
        #pragma unroll
        for (int o = 4; o; o >>= 1) {
            a += __shfl_xor_sync(0xffffffffu, a, o);
            b += __shfl_xor_sync(0xffffffffu, b, o);
        }
        if (lane == 0) { sh[0] = a; sh[1] = b; }
    }
    __syncthreads();
    const float mu   = sh[0] * (1.f / D_MODEL);
    const float var  = sh[1] * (1.f / D_MODEL) - mu * mu;
    const float rstd = rsqrtf(var + LN_EPS);
    #pragma unroll
    for (int i = 0; i < 3; i++) {
        const int idx = t + i * 256;
        y[base + idx] = (v[i] - mu) * rstd * gm[idx] + bt[idx];
    }
}

// ---------------- row softmax over length-1024 rows (one block per row) ----------------
__global__ void softmax_kernel(float* __restrict__ S)
{
    float* p = S + (long long)blockIdx.x * SEQ;
    const int t = threadIdx.x;
    const int wid = t >> 5, lane = t & 31;
    __shared__ float sh[8];

    float v[4];
    float mx = -3.4e38f;
    #pragma unroll
    for (int i = 0; i < 4; i++) { v[i] = p[t + i * 256]; mx = fmaxf(mx, v[i]); }
    #pragma unroll
    for (int o = 16; o; o >>= 1) mx = fmaxf(mx, __shfl_xor_sync(0xffffffffu, mx, o));
    if (lane == 0) sh[wid] = mx;
    __syncthreads();
    if (wid == 0) {
        float a = (lane < 8) ? sh[lane] : -3.4e38f;
        #pragma unroll
        for (int o = 4; o; o >>= 1) a = fmaxf(a, __shfl_xor_sync(0xffffffffu, a, o));
        if (lane == 0) sh[0] = a;
    }
    __syncthreads();
    mx = sh[0];
    __syncthreads();

    float s = 0.f;
    #pragma unroll
    for (int i = 0; i < 4; i++) { v[i] = __expf(v[i] - mx); s += v[i]; }
    #pragma unroll
    for (int o = 16; o; o >>= 1) s += __shfl_xor_sync(0xffffffffu, s, o);
    if (lane == 0) sh[wid] = s;
    __syncthreads();
    if (wid == 0) {
        float a = (lane < 8) ? sh[lane] : 0.f;
        #pragma unroll
        for (int o = 4; o; o >>= 1) a += __shfl_xor_sync(0xffffffffu, a, o);
        if (lane == 0) sh[0] = a;
    }
    __syncthreads();
    const float inv = 1.f / sh[0];
    #pragma unroll
    for (int i = 0; i < 4; i++) p[t + i * 256] = v[i] * inv;
}

// ---------------- launch ----------------
extern "C" void kernel_launch(void* const* d_in, const int* in_sizes, int n_in,
                              void* d_out, int out_size)
{
    const float* x    = (const float*)d_in[0];
    const float* Wq   = (const float*)d_in[1];
    const float* Wk   = (const float*)d_in[2];
    const float* Wv   = (const float*)d_in[3];
    const float* Wu   = (const float*)d_in[4];
    const float* bu   = (const float*)d_in[5];
    const float* ln1g = (const float*)d_in[6];
    const float* ln1b = (const float*)d_in[7];
    const float* ln2g = (const float*)d_in[8];
    const float* ln2b = (const float*)d_in[9];
    const float* W1   = (const float*)d_in[10];
    const float* b1   = (const float*)d_in[11];
    const float* W2   = (const float*)d_in[12];
    const float* b2   = (const float*)d_in[13];
    float* out = (float*)d_out;

    float *Y, *Q, *Kp, *V, *S, *ATT, *X1, *H1;
    cudaGetSymbolAddress((void**)&Y,   g_Y);
    cudaGetSymbolAddress((void**)&Q,   g_Q);
    cudaGetSymbolAddress((void**)&Kp,  g_K);
    cudaGetSymbolAddress((void**)&V,   g_V);
    cudaGetSymbolAddress((void**)&S,   g_S);
    cudaGetSymbolAddress((void**)&ATT, g_ATT);
    cudaGetSymbolAddress((void**)&X1,  g_X1);
    cudaGetSymbolAddress((void**)&H1,  g_H1);

    const float inv_sqrt_d = 0.03608439182435161f;     // 1/sqrt(768)

    // 1) LN1: x -> Y
    layernorm_kernel<<<NTOK, 256>>>(x, ln1g, ln1b, Y);

    // 2) Q/K/V = Y @ W{q,k,v}   (M=4096, N=9216, K=768)
    {
        dim3 grid(DH / 128, NTOK / 128, 1);
        gemm_tf32<false,false,false,false><<<grid, 256>>>(Y, Wq, nullptr, nullptr, Q,
            D_MODEL, D_MODEL, DH, DH, 0, 1.f, 0,0,0,0,0,0,0,0, 1);
        gemm_tf32<false,false,false,false><<<grid, 256>>>(Y, Wk, nullptr, nullptr, Kp,
            D_MODEL, D_MODEL, DH, DH, 0, 1.f, 0,0,0,0,0,0,0,0, 1);
        gemm_tf32<false,false,false,false><<<grid, 256>>>(Y, Wv, nullptr, nullptr, V,
            D_MODEL, D_MODEL, DH, DH, 0, 1.f, 0,0,0,0,0,0,0,0, 1);
    }

    // 3) S[b,h] = (Q_bh @ K_bh^T) / sqrt(768)   (M=N=1024, K=768, batch=48)
    {
        dim3 grid(SEQ / 128, SEQ / 128, BATCH * NHEAD);
        gemm_tf32<true,false,false,false><<<grid, 256>>>(Q, Kp, nullptr, nullptr, S,
            D_MODEL, DH, DH, SEQ, 0, inv_sqrt_d,
            (long long)SEQ * DH, (long long)D_MODEL,
            (long long)SEQ * DH, (long long)D_MODEL,
            (long long)NHEAD * SEQ * SEQ, (long long)SEQ * SEQ,
            0, 0, NHEAD);
    }

    // 4) softmax over rows of S
    softmax_kernel<<<BATCH * NHEAD * SEQ, 256>>>(S);

    // 5) ATT[b,:,h,:] = P_bh @ V_bh   (M=1024, N=768, K=1024, batch=48)
    {
        dim3 grid(D_MODEL / 128, SEQ / 128, BATCH * NHEAD);
        gemm_tf32<false,false,false,false><<<grid, 256>>>(S, V, nullptr, nullptr, ATT,
            SEQ, SEQ, DH, DH, 0, 1.f,
            (long long)NHEAD * SEQ * SEQ, (long long)SEQ * SEQ,
            (long long)SEQ * DH, (long long)D_MODEL,
            (long long)SEQ * DH, (long long)D_MODEL,
            0, 0, NHEAD);
    }

    // 6) X1 = ATT @ Wu + bu + x   (M=4096, N=768, K=9216)
    {
        dim3 grid(D_MODEL / 128, NTOK / 128, 1);
        gemm_tf32<false,false,true,true><<<grid, 256>>>(ATT, Wu, bu, x, X1,
            DH, DH, D_MODEL, D_MODEL, D_MODEL, 1.f, 0,0,0,0,0,0,0,0, 1);
    }

    // 7) LN2: X1 -> Y
    layernorm_kernel<<<NTOK, 256>>>(X1, ln2g, ln2b, Y);

    // 8) H1 = relu(Y @ W1 + b1)   (M=4096, N=3072, K=768)
    {
        dim3 grid(DFF / 128, NTOK / 128, 1);
        gemm_tf32<false,true,true,false><<<grid, 256>>>(Y, W1, b1, nullptr, H1,
            D_MODEL, D_MODEL, DFF, DFF, 0, 1.f, 0,0,0,0,0,0,0,0, 1);
    }

    // 9) out = H1 @ W2 + b2 + X1   (M=4096, N=768, K=3072)
    {
        dim3 grid(D_MODEL / 128, NTOK / 128, 1);
        gemm_tf32<false,false,true,true><<<grid, 256>>>(H1, W2, b2, X1, out,
            DFF, DFF, D_MODEL, D_MODEL, D_MODEL, 1.f, 0,0,0,0,0,0,0,0, 1);
    }

    (void)in_sizes; (void)n_in; (void)out_size;
}

// round 5
// speedup vs baseline: 1.6457x; 1.3452x over previous
#include <cuda_runtime.h>
#include <cstdint>

#define D_MODEL 768
#define NHEAD   12
#define SEQ     1024
#define BATCH   4
#define NTOK    (BATCH*SEQ)        /* 4096 */
#define DH      (D_MODEL*NHEAD)    /* 9216 */
#define DFF     (4*D_MODEL)        /* 3072 */
#define LN_EPS  1e-5f

typedef long long ll;

// ---------------- scratch (device globals; no allocation allowed) ----------------
__device__ float g_Y  [(size_t)NTOK * D_MODEL];
__device__ float g_Q  [(size_t)NTOK * DH];
__device__ float g_K  [(size_t)NTOK * DH];
__device__ float g_V  [(size_t)NTOK * DH];
__device__ float g_S  [(size_t)BATCH * NHEAD * SEQ * SEQ];   // scores; later aliased as split-K partials
__device__ float g_ATT[(size_t)NTOK * DH];
__device__ float g_X1 [(size_t)NTOK * D_MODEL];
__device__ float g_H1 [(size_t)NTOK * DFF];
// tf32-rounded weight copies
__device__ float g_WqR[(size_t)D_MODEL * DH];
__device__ float g_WkR[(size_t)D_MODEL * DH];
__device__ float g_WvR[(size_t)D_MODEL * DH];
__device__ float g_WuR[(size_t)DH * D_MODEL];
__device__ float g_W1R[(size_t)D_MODEL * DFF];
__device__ float g_W2R[(size_t)DFF * D_MODEL];

// ---------------- helpers ----------------
__device__ __forceinline__ float to_tf32(float x) {
    uint32_t u;
    asm("cvt.rna.tf32.f32 %0, %1;" : "=r"(u) : "f"(x));
    return __uint_as_float(u);
}
__device__ __forceinline__ uint32_t smem_u32(const void* p) {
    uint32_t a;
    asm("{ .reg .u64 t; cvta.to.shared.u64 t, %1; cvt.u32.u64 %0, t; }" : "=r"(a) : "l"(p));
    return a;
}
__device__ __forceinline__ void cp16(uint32_t dst, const void* src) {
    asm volatile("cp.async.cg.shared.global [%0], [%1], 16;" :: "r"(dst), "l"(src) : "memory");
}
__device__ __forceinline__ void cp_commit() {
    asm volatile("cp.async.commit_group;" ::: "memory");
}
__device__ __forceinline__ void cp_wait1() {
    asm volatile("cp.async.wait_group 1;" ::: "memory");
}
__device__ __forceinline__ void mma_tf32(float c[4],
                                         uint32_t a0, uint32_t a1, uint32_t a2, uint32_t a3,
                                         uint32_t b0, uint32_t b1) {
    asm("mma.sync.aligned.m16n8k8.row.col.f32.tf32.tf32.f32 "
        "{%0,%1,%2,%3}, {%4,%5,%6,%7}, {%8,%9}, {%0,%1,%2,%3};"
        : "+f"(c[0]), "+f"(c[1]), "+f"(c[2]), "+f"(c[3])
        : "r"(a0), "r"(a1), "r"(a2), "r"(a3), "r"(b0), "r"(b1));
}

// ---------------- tf32 tensor-core GEMM, cp.async 3-stage, warp tile 64x64 ----------
// C[m,n] = epi( alpha * sum_k A[m,k] * B(k,n) )
//   BT=false: B is K x N row-major (weights / V / P-V).  BT=true: B is N x K (A @ B^T).
// Tile: 128(M) x TN(N) x 32(K).  TN=256 -> 8 warps (2x4), TN=128 -> 4 warps (2x2).
// Inputs are pre-rounded to tf32 by producers; no conversion here.
// smem A: [m][k] pitch 36 floats.  B NN: [k][n] pitch TN+8.  B NT: [n][k] pitch 36.
// All consumer LDS.32 gathers are 32-bank conflict-free by construction.
template<int TN, bool BT, bool RELU, bool HASB, bool HASR, bool ROUND>
__global__ __launch_bounds__(TN == 256 ? 256 : 128, 1)
void gemm_cp(const float* __restrict__ A, const float* __restrict__ B,
             const float* __restrict__ bias, const float* __restrict__ Res,
             float* __restrict__ C,
             int K, int lda, int ldb, int ldc, int ldr, float alpha,
             ll saO, ll saI, ll sbO, ll sbI, ll scO, ll scI, ll srO, ll srI,
             int innerCnt)
{
    constexpr int THREADS = (TN == 256) ? 256 : 128;
    constexpr int A_F     = 128 * 36;                        // floats per A stage
    constexpr int B_F     = BT ? TN * 36 : 32 * (TN + 8);
    constexpr int STAGE_F = A_F + B_F;
    constexpr int A_PER   = 1024 / THREADS;                  // float4 per thread for A
    constexpr int B_PER   = (TN * 8) / THREADS;              // float4 per thread for B
    constexpr int PB      = TN + 8;

    extern __shared__ float dynsm[];

    const int tid  = threadIdx.x;
    const int wid  = tid >> 5;
    const int lane = tid & 31;
    const int g    = lane >> 2;
    const int tig  = lane & 3;
    const int wm   = (TN == 256) ? (wid >> 2) : (wid >> 1);
    const int wn   = (TN == 256) ? (wid & 3)  : (wid & 1);

    const int z  = blockIdx.z;
    const int zo = z / innerCnt;
    const int zi = z - zo * innerCnt;
    A += zo * saO + zi * saI;
    B += zo * sbO + zi * sbI;
    C += zo * scO + zi * scI;
    if (HASR) Res += zo * srO + zi * srI;

    const int m0 = blockIdx.y * 128;
    const int n0 = blockIdx.x * TN;
    A += (ll)m0 * lda;
    B += BT ? (ll)n0 * ldb : (ll)n0;

    const uint32_t smb = smem_u32(dynsm);

    auto issue = [&](int tile) {
        const int stage = tile % 3;
        const uint32_t sA = smb + (uint32_t)(stage * STAGE_F) * 4u;
        const uint32_t sB = sA + (uint32_t)A_F * 4u;
        const int k0 = tile * 32;
        #pragma unroll
        for (int i = 0; i < A_PER; i++) {
            const int v = tid + i * THREADS;
            const int m = v >> 3, kc = (v & 7) * 4;
            cp16(sA + (uint32_t)(m * 36 + kc) * 4u, A + (ll)m * lda + k0 + kc);
        }
        #pragma unroll
        for (int i = 0; i < B_PER; i++) {
            const int v = tid + i * THREADS;
            if (BT) {
                const int n = v >> 3, kc = (v & 7) * 4;
                cp16(sB + (uint32_t)(n * 36 + kc) * 4u, B + (ll)n * ldb + k0 + kc);
            } else {
                const int k = v / (TN / 4), nc = (v % (TN / 4)) * 4;
                cp16(sB + (uint32_t)(k * PB + nc) * 4u, B + (ll)(k0 + k) * ldb + nc);
            }
        }
        cp_commit();
    };

    float acc[4][8][4];
    #pragma unroll
    for (int mt = 0; mt < 4; mt++)
        #pragma unroll
        for (int nt = 0; nt < 8; nt++)
            #pragma unroll
            for (int r = 0; r < 4; r++) acc[mt][nt][r] = 0.f;

    const int T = K >> 5;
    issue(0);
    issue(1);

    for (int it = 0; it < T; ++it) {
        cp_wait1();
        __syncthreads();
        if (it + 2 < T) issue(it + 2);

        const float* As  = dynsm + (it % 3) * STAGE_F;
        const float* Bsm = As + A_F;

        #pragma unroll
        for (int ksi = 0; ksi < 4; ksi++) {
            const int kk = ksi * 8 + tig;
            uint32_t a[4][4], b[8][2];
            #pragma unroll
            for (int mt = 0; mt < 4; mt++) {
                const int mA = wm * 64 + mt * 16 + g;
                a[mt][0] = __float_as_uint(As[(mA    ) * 36 + kk    ]);
                a[mt][1] = __float_as_uint(As[(mA + 8) * 36 + kk    ]);
                a[mt][2] = __float_as_uint(As[(mA    ) * 36 + kk + 4]);
                a[mt][3] = __float_as_uint(As[(mA + 8) * 36 + kk + 4]);
            }
            #pragma unroll
            for (int nt = 0; nt < 8; nt++) {
                const int nB = wn * 64 + nt * 8 + g;
                if (BT) {
                    b[nt][0] = __float_as_uint(Bsm[nB * 36 + kk    ]);
                    b[nt][1] = __float_as_uint(Bsm[nB * 36 + kk + 4]);
                } else {
                    b[nt][0] = __float_as_uint(Bsm[(kk    ) * PB + nB]);
                    b[nt][1] = __float_as_uint(Bsm[(kk + 4) * PB + nB]);
                }
            }
            #pragma unroll
            for (int mt = 0; mt < 4; mt++)
                #pragma unroll
                for (int nt = 0; nt < 8; nt++)
                    mma_tf32(acc[mt][nt], a[mt][0], a[mt][1], a[mt][2], a[mt][3],
                             b[nt][0], b[nt][1]);
        }
        __syncthreads();
    }

    // ---- epilogue ----
    #pragma unroll
    for (int mt = 0; mt < 4; mt++) {
        #pragma unroll
        for (int nt = 0; nt < 8; nt++) {
            const int n = n0 + wn * 64 + nt * 8 + tig * 2;
            float bv0 = 0.f, bv1 = 0.f;
            if (HASB) { bv0 = bias[n]; bv1 = bias[n + 1]; }
            #pragma unroll
            for (int h = 0; h < 2; h++) {
                const int m = m0 + wm * 64 + mt * 16 + g + h * 8;
                float x0 = alpha * acc[mt][nt][h * 2 + 0] + bv0;
                float x1 = alpha * acc[mt][nt][h * 2 + 1] + bv1;
                if (RELU) { x0 = fmaxf(x0, 0.f); x1 = fmaxf(x1, 0.f); }
                if (HASR) {
                    x0 += Res[(ll)m * ldr + n];
                    x1 += Res[(ll)m * ldr + n + 1];
                }
                if (ROUND) { x0 = to_tf32(x0); x1 = to_tf32(x1); }
                float2 w; w.x = x0; w.y = x1;
                *reinterpret_cast<float2*>(C + (ll)m * ldc + n) = w;
            }
        }
    }
}

// ---------------- tf32 rounding copy (weights) ----------------
__global__ void round_copy_kernel(const float4* __restrict__ in, float4* __restrict__ out, int n4)
{
    const int i = blockIdx.x * blockDim.x + threadIdx.x;
    if (i >= n4) return;
    float4 v = in[i];
    v.x = to_tf32(v.x); v.y = to_tf32(v.y); v.z = to_tf32(v.z); v.w = to_tf32(v.w);
    out[i] = v;
}

// ---------------- split-K combine: out = P0 + P1 + bias + res ----------------
__global__ void combine_kernel(const float4* __restrict__ P0, const float4* __restrict__ P1,
                               const float* __restrict__ bias, const float4* __restrict__ res,
                               float4* __restrict__ out, int n4)
{
    const int i = blockIdx.x * blockDim.x + threadIdx.x;
    if (i >= n4) return;
    const int c = (i % (D_MODEL / 4)) * 4;
    const float4 p = P0[i], q = P1[i], r = res[i];
    float4 o;
    o.x = p.x + q.x + bias[c + 0] + r.x;
    o.y = p.y + q.y + bias[c + 1] + r.y;
    o.z = p.z + q.z + bias[c + 2] + r.z;
    o.w = p.w + q.w + bias[c + 3] + r.w;
    out[i] = o;
}

// ---------------- layernorm (rounds output to tf32: it feeds GEMM A) ----------------
__global__ void layernorm_kernel(const float* __restrict__ x,
                                 const float* __restrict__ gm,
                                 const float* __restrict__ bt,
                                 float* __restrict__ y)
{
    const ll base = (ll)blockIdx.x * D_MODEL;
    const int t = threadIdx.x;
    float v[3];
    float lsum = 0.f, lsq = 0.f;
    #pragma unroll
    for (int i = 0; i < 3; i++) {
        v[i] = x[base + t + i * 256];
        lsum += v[i];
        lsq  += v[i] * v[i];
    }
    __shared__ float sh[16];
    #pragma unroll
    for (int o = 16; o; o >>= 1) {
        lsum += __shfl_xor_sync(0xffffffffu, lsum, o);
        lsq  += __shfl_xor_sync(0xffffffffu, lsq,  o);
    }
    const int wid = t >> 5, lane = t & 31;
    if (lane == 0) { sh[wid] = lsum; sh[8 + wid] = lsq; }
    __syncthreads();
    if (wid == 0) {
        float a = (lane < 8) ? sh[lane] : 0.f;
        float b = (lane < 8) ? sh[8 + lane] : 0.f;
        #pragma unroll
        for (int o = 4; o; o >>= 1) {
            a += __shfl_xor_sync(0xffffffffu, a, o);
            b += __shfl_xor_sync(0xffffffffu, b, o);
        }
        if (lane == 0) { sh[0] = a; sh[1] = b; }
    }
    __syncthreads();
    const float mu   = sh[0] * (1.f / D_MODEL);
    const float var  = sh[1] * (1.f / D_MODEL) - mu * mu;
    const float rstd = rsqrtf(var + LN_EPS);
    #pragma unroll
    for (int i = 0; i < 3; i++) {
        const int idx = t + i * 256;
        y[base + idx] = to_tf32((v[i] - mu) * rstd * gm[idx] + bt[idx]);
    }
}

// ---------------- row softmax over length-1024 rows (rounds output to tf32) --------
__global__ void softmax_kernel(float* __restrict__ S)
{
    float* p = S + (ll)blockIdx.x * SEQ;
    const int t = threadIdx.x;
    const int wid = t >> 5, lane = t & 31;
    __shared__ float sh[8];

    float v[4];
    float mx = -3.4e38f;
    #pragma unroll
    for (int i = 0; i < 4; i++) { v[i] = p[t + i * 256]; mx = fmaxf(mx, v[i]); }
    #pragma unroll
    for (int o = 16; o; o >>= 1) mx = fmaxf(mx, __shfl_xor_sync(0xffffffffu, mx, o));
    if (lane == 0) sh[wid] = mx;
    __syncthreads();
    if (wid == 0) {
        float a = (lane < 8) ? sh[lane] : -3.4e38f;
        #pragma unroll
        for (int o = 4; o; o >>= 1) a = fmaxf(a, __shfl_xor_sync(0xffffffffu, a, o));
        if (lane == 0) sh[0] = a;
    }
    __syncthreads();
    mx = sh[0];
    __syncthreads();

    float s = 0.f;
    #pragma unroll
    for (int i = 0; i < 4; i++) { v[i] = __expf(v[i] - mx); s += v[i]; }
    #pragma unroll
    for (int o = 16; o; o >>= 1) s += __shfl_xor_sync(0xffffffffu, s, o);
    if (lane == 0) sh[wid] = s;
    __syncthreads();
    if (wid == 0) {
        float a = (lane < 8) ? sh[lane] : 0.f;
        #pragma unroll
        for (int o = 4; o; o >>= 1) a += __shfl_xor_sync(0xffffffffu, a, o);
        if (lane == 0) sh[0] = a;
    }
    __syncthreads();
    const float inv = 1.f / sh[0];
    #pragma unroll
    for (int i = 0; i < 4; i++) p[t + i * 256] = to_tf32(v[i] * inv);
}

// ---------------- launch ----------------
// smem sizes: stage_floats*3*4 bytes
#define SMEM_NN256 156672   /* (4608 + 32*264)*3*4 */
#define SMEM_NT256 165888   /* (4608 + 256*36)*3*4 */
#define SMEM_NN128 107520   /* (4608 + 32*136)*3*4 */

extern "C" void kernel_launch(void* const* d_in, const int* in_sizes, int n_in,
                              void* d_out, int out_size)
{
    const float* x    = (const float*)d_in[0];
    const float* Wq   = (const float*)d_in[1];
    const float* Wk   = (const float*)d_in[2];
    const float* Wv   = (const float*)d_in[3];
    const float* Wu   = (const float*)d_in[4];
    const float* bu   = (const float*)d_in[5];
    const float* ln1g = (const float*)d_in[6];
    const float* ln1b = (const float*)d_in[7];
    const float* ln2g = (const float*)d_in[8];
    const float* ln2b = (const float*)d_in[9];
    const float* W1   = (const float*)d_in[10];
    const float* b1   = (const float*)d_in[11];
    const float* W2   = (const float*)d_in[12];
    const float* b2   = (const float*)d_in[13];
    float* out = (float*)d_out;

    float *Y, *Q, *Kp, *V, *S, *ATT, *X1, *H1;
    float *WqR, *WkR, *WvR, *WuR, *W1R, *W2R;
    cudaGetSymbolAddress((void**)&Y,   g_Y);
    cudaGetSymbolAddress((void**)&Q,   g_Q);
    cudaGetSymbolAddress((void**)&Kp,  g_K);
    cudaGetSymbolAddress((void**)&V,   g_V);
    cudaGetSymbolAddress((void**)&S,   g_S);
    cudaGetSymbolAddress((void**)&ATT, g_ATT);
    cudaGetSymbolAddress((void**)&X1,  g_X1);
    cudaGetSymbolAddress((void**)&H1,  g_H1);
    cudaGetSymbolAddress((void**)&WqR, g_WqR);
    cudaGetSymbolAddress((void**)&WkR, g_WkR);
    cudaGetSymbolAddress((void**)&WvR, g_WvR);
    cudaGetSymbolAddress((void**)&WuR, g_WuR);
    cudaGetSymbolAddress((void**)&W1R, g_W1R);
    cudaGetSymbolAddress((void**)&W2R, g_W2R);

    // split-K partial buffers alias g_S (dead after PV GEMM)
    float* P0 = S;
    float* P1 = S + (size_t)NTOK * D_MODEL;

    cudaFuncSetAttribute(gemm_cp<256,false,false,false,false,true >, cudaFuncAttributeMaxDynamicSharedMemorySize, SMEM_NN256);
    cudaFuncSetAttribute(gemm_cp<256,true ,false,false,false,false>, cudaFuncAttributeMaxDynamicSharedMemorySize, SMEM_NT256);
    cudaFuncSetAttribute(gemm_cp<256,false,true ,true ,false,true >, cudaFuncAttributeMaxDynamicSharedMemorySize, SMEM_NN256);
    cudaFuncSetAttribute(gemm_cp<128,false,false,false,false,false>, cudaFuncAttributeMaxDynamicSharedMemorySize, SMEM_NN128);

    const float inv_sqrt_d = 0.03608439182435161f;   // 1/sqrt(768)

    // 0) LN1 + weight rounding copies
    layernorm_kernel<<<NTOK, 256>>>(x, ln1g, ln1b, Y);
    {
        const int nqkv = D_MODEL * DH / 4, nmlp = D_MODEL * DFF / 4;
        round_copy_kernel<<<(nqkv + 255) / 256, 256>>>((const float4*)Wq, (float4*)WqR, nqkv);
        round_copy_kernel<<<(nqkv + 255) / 256, 256>>>((const float4*)Wk, (float4*)WkR, nqkv);
        round_copy_kernel<<<(nqkv + 255) / 256, 256>>>((const float4*)Wv, (float4*)WvR, nqkv);
        round_copy_kernel<<<(nqkv + 255) / 256, 256>>>((const float4*)Wu, (float4*)WuR, nqkv);
        round_copy_kernel<<<(nmlp + 255) / 256, 256>>>((const float4*)W1, (float4*)W1R, nmlp);
        round_copy_kernel<<<(nmlp + 255) / 256, 256>>>((const float4*)W2, (float4*)W2R, nmlp);
    }

    // 1) Q/K/V = Y @ W{q,k,v}  (M=4096, N=9216, K=768) — outputs rounded (GEMM operands)
    {
        dim3 grid(DH / 256, NTOK / 128, 1);
        gemm_cp<256,false,false,false,false,true><<<grid, 256, SMEM_NN256>>>(Y, WqR, nullptr, nullptr, Q,
            D_MODEL, D_MODEL, DH, DH, 0, 1.f, 0,0,0,0,0,0,0,0, 1);
        gemm_cp<256,false,false,false,false,true><<<grid, 256, SMEM_NN256>>>(Y, WkR, nullptr, nullptr, Kp,
            D_MODEL, D_MODEL, DH, DH, 0, 1.f, 0,0,0,0,0,0,0,0, 1);
        gemm_cp<256,false,false,false,false,true><<<grid, 256, SMEM_NN256>>>(Y, WvR, nullptr, nullptr, V,
            D_MODEL, D_MODEL, DH, DH, 0, 1.f, 0,0,0,0,0,0,0,0, 1);
    }

    // 2) S[b,h] = (Q_bh @ K_bh^T)/sqrt(768)  (M=N=1024, K=768, batch=48; NT)
    {
        dim3 grid(SEQ / 256, SEQ / 128, BATCH * NHEAD);
        gemm_cp<256,true,false,false,false,false><<<grid, 256, SMEM_NT256>>>(Q, Kp, nullptr, nullptr, S,
            D_MODEL, DH, DH, SEQ, 0, inv_sqrt_d,
            (ll)SEQ * DH, (ll)D_MODEL,
            (ll)SEQ * DH, (ll)D_MODEL,
            (ll)NHEAD * SEQ * SEQ, (ll)SEQ * SEQ,
            0, 0, NHEAD);
    }

    // 3) softmax (rounds P to tf32)
    softmax_kernel<<<BATCH * NHEAD * SEQ, 256>>>(S);

    // 4) ATT[b,:,h,:] = P_bh @ V_bh  (M=1024, N=768, K=1024, batch=48; NN) — rounded out
    {
        dim3 grid(D_MODEL / 256, SEQ / 128, BATCH * NHEAD);
        gemm_cp<256,false,false,false,false,true><<<grid, 256, SMEM_NN256>>>(S, V, nullptr, nullptr, ATT,
            SEQ, SEQ, DH, DH, 0, 1.f,
            (ll)NHEAD * SEQ * SEQ, (ll)SEQ * SEQ,
            (ll)SEQ * DH, (ll)D_MODEL,
            (ll)SEQ * DH, (ll)D_MODEL,
            0, 0, NHEAD);
    }

    // 5) Wu split-K=2: partials, then X1 = P0 + P1 + bu + x
    {
        dim3 grid(D_MODEL / 128, NTOK / 128, 1);
        gemm_cp<128,false,false,false,false,false><<<grid, 128, SMEM_NN128>>>(ATT, WuR,
            nullptr, nullptr, P0, DH/2, DH, D_MODEL, D_MODEL, 0, 1.f, 0,0,0,0,0,0,0,0, 1);
        gemm_cp<128,false,false,false,false,false><<<grid, 128, SMEM_NN128>>>(ATT + DH/2, WuR + (ll)(DH/2) * D_MODEL,
            nullptr, nullptr, P1, DH/2, DH, D_MODEL, D_MODEL, 0, 1.f, 0,0,0,0,0,0,0,0, 1);
        const int n4 = NTOK * D_MODEL / 4;
        combine_kernel<<<(n4 + 255) / 256, 256>>>((const float4*)P0, (const float4*)P1, bu,
                                                  (const float4*)x, (float4*)X1, n4);
    }

    // 6) LN2
    layernorm_kernel<<<NTOK, 256>>>(X1, ln2g, ln2b, Y);

    // 7) H1 = relu(Y @ W1 + b1)  (M=4096, N=3072, K=768) — rounded out
    {
        dim3 grid(DFF / 256, NTOK / 128, 1);
        gemm_cp<256,false,true,true,false,true><<<grid, 256, SMEM_NN256>>>(Y, W1R, b1, nullptr, H1,
            D_MODEL, D_MODEL, DFF, DFF, 0, 1.f, 0,0,0,0,0,0,0,0, 1);
    }

    // 8) W2 split-K=2: partials, then out = P0 + P1 + b2 + X1
    {
        dim3 grid(D_MODEL / 128, NTOK / 128, 1);
        gemm_cp<128,false,false,false,false,false><<<grid, 128, SMEM_NN128>>>(H1, W2R,
            nullptr, nullptr, P0, DFF/2, DFF, D_MODEL, D_MODEL, 0, 1.f, 0,0,0,0,0,0,0,0, 1);
        gemm_cp<128,false,false,false,false,false><<<grid, 128, SMEM_NN128>>>(H1 + DFF/2, W2R + (ll)(DFF/2) * D_MODEL,
            nullptr, nullptr, P1, DFF/2, DFF, D_MODEL, D_MODEL, 0, 1.f, 0,0,0,0,0,0,0,0, 1);
        const int n4 = NTOK * D_MODEL / 4;
        combine_kernel<<<(n4 + 255) / 256, 256>>>((const float4*)P0, (const float4*)P1, b2,
                                                  (const float4*)X1, (float4*)out, n4);
    }

    (void)in_sizes; (void)n_in; (void)out_size;
}

// round 6
// speedup vs baseline: 1.6690x; 1.0142x over previous
#include <cuda_runtime.h>
#include <cstdint>

#define D_MODEL 768
#define NHEAD   12
#define SEQ     1024
#define BATCH   4
#define NTOK    (BATCH*SEQ)        /* 4096 */
#define DH      (D_MODEL*NHEAD)    /* 9216 */
#define DFF     (4*D_MODEL)        /* 3072 */
#define LN_EPS  1e-5f

typedef long long ll;

// ---------------- scratch (device globals; no allocation allowed) ----------------
__device__ float g_Y  [(size_t)NTOK * D_MODEL];
__device__ float g_Q  [(size_t)NTOK * DH];
__device__ float g_K  [(size_t)NTOK * DH];
__device__ float g_V  [(size_t)NTOK * DH];
__device__ float g_S  [(size_t)BATCH * NHEAD * SEQ * SEQ];   // scores; later aliased as split-K partials
__device__ float g_ATT[(size_t)NTOK * DH];
__device__ float g_X1 [(size_t)NTOK * D_MODEL];
__device__ float g_H1 [(size_t)NTOK * DFF];

// ---------------- helpers ----------------
__device__ __forceinline__ float to_tf32(float x) {
    uint32_t u;
    asm("cvt.rna.tf32.f32 %0, %1;" : "=r"(u) : "f"(x));
    return __uint_as_float(u);
}
__device__ __forceinline__ uint32_t smem_u32(const void* p) {
    uint32_t a;
    asm("{ .reg .u64 t; cvta.to.shared.u64 t, %1; cvt.u32.u64 %0, t; }" : "=r"(a) : "l"(p));
    return a;
}
__device__ __forceinline__ void cp16(uint32_t dst, const void* src) {
    asm volatile("cp.async.cg.shared.global [%0], [%1], 16;" :: "r"(dst), "l"(src) : "memory");
}
__device__ __forceinline__ void cp_commit() {
    asm volatile("cp.async.commit_group;" ::: "memory");
}
template<int N>
__device__ __forceinline__ void cp_wait() {
    asm volatile("cp.async.wait_group %0;" :: "n"(N) : "memory");
}
__device__ __forceinline__ void mma_tf32(float c[4],
                                         uint32_t a0, uint32_t a1, uint32_t a2, uint32_t a3,
                                         uint32_t b0, uint32_t b1) {
    asm("mma.sync.aligned.m16n8k8.row.col.f32.tf32.tf32.f32 "
        "{%0,%1,%2,%3}, {%4,%5,%6,%7}, {%8,%9}, {%0,%1,%2,%3};"
        : "+f"(c[0]), "+f"(c[1]), "+f"(c[2]), "+f"(c[3])
        : "r"(a0), "r"(a1), "r"(a2), "r"(a3), "r"(b0), "r"(b1));
}

// ---------------- tf32 tensor-core GEMM, cp.async multi-stage, warp tile 64x64 ------
// C[m,n] = epi( alpha * sum_k A[m,k] * B(k,n) )
//   BT=false: B is K x N row-major.  BT=true: B is N x K row-major (A @ B^T).
// Tile: 128(M) x TN(N) x 32(K).  TN=256 -> 8 warps (2x4), TN=128 -> 4 warps (2x2).
// A operand rounding: activations pre-rounded by producers; weights rely on HW
// tf32 truncation inside mma.sync (adds ~1e-4 sign-symmetric bias, within budget).
// smem A: [m][k] pitch 36.  B NN: [k][n] pitch TN+8.  B NT: [n][k] pitch 36.
// One __syncthreads per k-tile: top-of-loop barrier orders compute(it-1) reads
// before issue(it+STAGES-1) overwrites stage (it-1)%STAGES.
template<int TN, int STAGES, bool BT, bool RELU, bool HASB, bool HASR, bool ROUND>
__global__ __launch_bounds__(TN == 256 ? 256 : 128, 1)
void gemm_cp(const float* __restrict__ A, const float* __restrict__ B,
             const float* __restrict__ bias, const float* __restrict__ Res,
             float* __restrict__ C,
             int K, int lda, int ldb, int ldc, int ldr, float alpha,
             ll saO, ll saI, ll sbO, ll sbI, ll scO, ll scI, ll srO, ll srI,
             int innerCnt)
{
    constexpr int THREADS = (TN == 256) ? 256 : 128;
    constexpr int A_F     = 128 * 36;
    constexpr int B_F     = BT ? TN * 36 : 32 * (TN + 8);
    constexpr int STAGE_F = A_F + B_F;
    constexpr int A_PER   = 1024 / THREADS;
    constexpr int B_PER   = (TN * 8) / THREADS;
    constexpr int PB      = TN + 8;

    extern __shared__ float dynsm[];

    const int tid  = threadIdx.x;
    const int wid  = tid >> 5;
    const int lane = tid & 31;
    const int g    = lane >> 2;
    const int tig  = lane & 3;
    const int wm   = (TN == 256) ? (wid >> 2) : (wid >> 1);
    const int wn   = (TN == 256) ? (wid & 3)  : (wid & 1);

    const int z  = blockIdx.z;
    const int zo = z / innerCnt;
    const int zi = z - zo * innerCnt;
    A += zo * saO + zi * saI;
    B += zo * sbO + zi * sbI;
    C += zo * scO + zi * scI;
    if (HASR) Res += zo * srO + zi * srI;

    const int m0 = blockIdx.y * 128;
    const int n0 = blockIdx.x * TN;
    A += (ll)m0 * lda;
    B += BT ? (ll)n0 * ldb : (ll)n0;

    const uint32_t smb = smem_u32(dynsm);

    auto issue = [&](int tile) {
        const int stage = tile % STAGES;
        const uint32_t sA = smb + (uint32_t)(stage * STAGE_F) * 4u;
        const uint32_t sB = sA + (uint32_t)A_F * 4u;
        const int k0 = tile * 32;
        #pragma unroll
        for (int i = 0; i < A_PER; i++) {
            const int v = tid + i * THREADS;
            const int m = v >> 3, kc = (v & 7) * 4;
            cp16(sA + (uint32_t)(m * 36 + kc) * 4u, A + (ll)m * lda + k0 + kc);
        }
        #pragma unroll
        for (int i = 0; i < B_PER; i++) {
            const int v = tid + i * THREADS;
            if (BT) {
                const int n = v >> 3, kc = (v & 7) * 4;
                cp16(sB + (uint32_t)(n * 36 + kc) * 4u, B + (ll)n * ldb + k0 + kc);
            } else {
                const int k = v / (TN / 4), nc = (v % (TN / 4)) * 4;
                cp16(sB + (uint32_t)(k * PB + nc) * 4u, B + (ll)(k0 + k) * ldb + nc);
            }
        }
        cp_commit();
    };

    float acc[4][8][4];
    #pragma unroll
    for (int mt = 0; mt < 4; mt++)
        #pragma unroll
        for (int nt = 0; nt < 8; nt++)
            #pragma unroll
            for (int r = 0; r < 4; r++) acc[mt][nt][r] = 0.f;

    const int T = K >> 5;
    #pragma unroll
    for (int s = 0; s < STAGES - 1; s++) issue(s);

    for (int it = 0; it < T; ++it) {
        cp_wait<STAGES - 2>();
        __syncthreads();
        if (it + STAGES - 1 < T) issue(it + STAGES - 1);

        const float* As  = dynsm + (it % STAGES) * STAGE_F;
        const float* Bsm = As + A_F;

        #pragma unroll
        for (int ksi = 0; ksi < 4; ksi++) {
            const int kk = ksi * 8 + tig;
            uint32_t a[4][4], b[8][2];
            #pragma unroll
            for (int mt = 0; mt < 4; mt++) {
                const int mA = wm * 64 + mt * 16 + g;
                a[mt][0] = __float_as_uint(As[(mA    ) * 36 + kk    ]);
                a[mt][1] = __float_as_uint(As[(mA + 8) * 36 + kk    ]);
                a[mt][2] = __float_as_uint(As[(mA    ) * 36 + kk + 4]);
                a[mt][3] = __float_as_uint(As[(mA + 8) * 36 + kk + 4]);
            }
            #pragma unroll
            for (int nt = 0; nt < 8; nt++) {
                const int nB = wn * 64 + nt * 8 + g;
                if (BT) {
                    b[nt][0] = __float_as_uint(Bsm[nB * 36 + kk    ]);
                    b[nt][1] = __float_as_uint(Bsm[nB * 36 + kk + 4]);
                } else {
                    b[nt][0] = __float_as_uint(Bsm[(kk    ) * PB + nB]);
                    b[nt][1] = __float_as_uint(Bsm[(kk + 4) * PB + nB]);
                }
            }
            #pragma unroll
            for (int mt = 0; mt < 4; mt++)
                #pragma unroll
                for (int nt = 0; nt < 8; nt++)
                    mma_tf32(acc[mt][nt], a[mt][0], a[mt][1], a[mt][2], a[mt][3],
                             b[nt][0], b[nt][1]);
        }
    }

    // ---- epilogue ----
    #pragma unroll
    for (int mt = 0; mt < 4; mt++) {
        #pragma unroll
        for (int nt = 0; nt < 8; nt++) {
            const int n = n0 + wn * 64 + nt * 8 + tig * 2;
            float bv0 = 0.f, bv1 = 0.f;
            if (HASB) { bv0 = bias[n]; bv1 = bias[n + 1]; }
            #pragma unroll
            for (int h = 0; h < 2; h++) {
                const int m = m0 + wm * 64 + mt * 16 + g + h * 8;
                float x0 = alpha * acc[mt][nt][h * 2 + 0] + bv0;
                float x1 = alpha * acc[mt][nt][h * 2 + 1] + bv1;
                if (RELU) { x0 = fmaxf(x0, 0.f); x1 = fmaxf(x1, 0.f); }
                if (HASR) {
                    x0 += Res[(ll)m * ldr + n];
                    x1 += Res[(ll)m * ldr + n + 1];
                }
                if (ROUND) { x0 = to_tf32(x0); x1 = to_tf32(x1); }
                float2 w; w.x = x0; w.y = x1;
                *reinterpret_cast<float2*>(C + (ll)m * ldc + n) = w;
            }
        }
    }
}

// ---------------- split-K combine: out = P0 + P1 + bias + res ----------------
__global__ void combine_kernel(const float4* __restrict__ P0, const float4* __restrict__ P1,
                               const float* __restrict__ bias, const float4* __restrict__ res,
                               float4* __restrict__ out, int n4)
{
    const int i = blockIdx.x * blockDim.x + threadIdx.x;
    if (i >= n4) return;
    const int c = (i % (D_MODEL / 4)) * 4;
    const float4 p = P0[i], q = P1[i], r = res[i];
    float4 o;
    o.x = p.x + q.x + bias[c + 0] + r.x;
    o.y = p.y + q.y + bias[c + 1] + r.y;
    o.z = p.z + q.z + bias[c + 2] + r.z;
    o.w = p.w + q.w + bias[c + 3] + r.w;
    out[i] = o;
}

// ---------------- layernorm (rounds output to tf32: it feeds GEMM A) ----------------
__global__ void layernorm_kernel(const float* __restrict__ x,
                                 const float* __restrict__ gm,
                                 const float* __restrict__ bt,
                                 float* __restrict__ y)
{
    const ll base = (ll)blockIdx.x * D_MODEL;
    const int t = threadIdx.x;
    float v[3];
    float lsum = 0.f, lsq = 0.f;
    #pragma unroll
    for (int i = 0; i < 3; i++) {
        v[i] = x[base + t + i * 256];
        lsum += v[i];
        lsq  += v[i] * v[i];
    }
    __shared__ float sh[16];
    #pragma unroll
    for (int o = 16; o; o >>= 1) {
        lsum += __shfl_xor_sync(0xffffffffu, lsum, o);
        lsq  += __shfl_xor_sync(0xffffffffu, lsq,  o);
    }
    const int wid = t >> 5, lane = t & 31;
    if (lane == 0) { sh[wid] = lsum; sh[8 + wid] = lsq; }
    __syncthreads();
    if (wid == 0) {
        float a = (lane < 8) ? sh[lane] : 0.f;
        float b = (lane < 8) ? sh[8 + lane] : 0.f;
        #pragma unroll
        for (int o = 4; o; o >>= 1) {
            a += __shfl_xor_sync(0xffffffffu, a, o);
            b += __shfl_xor_sync(0xffffffffu, b, o);
        }
        if (lane == 0) { sh[0] = a; sh[1] = b; }
    }
    __syncthreads();
    const float mu   = sh[0] * (1.f / D_MODEL);
    const float var  = sh[1] * (1.f / D_MODEL) - mu * mu;
    const float rstd = rsqrtf(var + LN_EPS);
    #pragma unroll
    for (int i = 0; i < 3; i++) {
        const int idx = t + i * 256;
        y[base + idx] = to_tf32((v[i] - mu) * rstd * gm[idx] + bt[idx]);
    }
}

// ---------------- row softmax over length-1024 rows (rounds output to tf32) --------
__global__ void softmax_kernel(float* __restrict__ S)
{
    float* p = S + (ll)blockIdx.x * SEQ;
    const int t = threadIdx.x;
    const int wid = t >> 5, lane = t & 31;
    __shared__ float sh[8];

    float v[4];
    float mx = -3.4e38f;
    #pragma unroll
    for (int i = 0; i < 4; i++) { v[i] = p[t + i * 256]; mx = fmaxf(mx, v[i]); }
    #pragma unroll
    for (int o = 16; o; o >>= 1) mx = fmaxf(mx, __shfl_xor_sync(0xffffffffu, mx, o));
    if (lane == 0) sh[wid] = mx;
    __syncthreads();
    if (wid == 0) {
        float a = (lane < 8) ? sh[lane] : -3.4e38f;
        #pragma unroll
        for (int o = 4; o; o >>= 1) a = fmaxf(a, __shfl_xor_sync(0xffffffffu, a, o));
        if (lane == 0) sh[0] = a;
    }
    __syncthreads();
    mx = sh[0];
    __syncthreads();

    float s = 0.f;
    #pragma unroll
    for (int i = 0; i < 4; i++) { v[i] = __expf(v[i] - mx); s += v[i]; }
    #pragma unroll
    for (int o = 16; o; o >>= 1) s += __shfl_xor_sync(0xffffffffu, s, o);
    if (lane == 0) sh[wid] = s;
    __syncthreads();
    if (wid == 0) {
        float a = (lane < 8) ? sh[lane] : 0.f;
        #pragma unroll
        for (int o = 4; o; o >>= 1) a += __shfl_xor_sync(0xffffffffu, a, o);
        if (lane == 0) sh[0] = a;
    }
    __syncthreads();
    const float inv = 1.f / sh[0];
    #pragma unroll
    for (int i = 0; i < 4; i++) p[t + i * 256] = to_tf32(v[i] * inv);
}

// ---------------- launch ----------------
// smem bytes = STAGE_F * STAGES * 4
#define SMEM_NN256 208896   /* (4608 + 32*264)*4st*4B */
#define SMEM_NT256 221184   /* (4608 + 256*36)*4st*4B */
#define SMEM_NN128 107520   /* (4608 + 32*136)*3st*4B  -> 2 CTAs/SM */

extern "C" void kernel_launch(void* const* d_in, const int* in_sizes, int n_in,
                              void* d_out, int out_size)
{
    const float* x    = (const float*)d_in[0];
    const float* Wq   = (const float*)d_in[1];
    const float* Wk   = (const float*)d_in[2];
    const float* Wv   = (const float*)d_in[3];
    const float* Wu   = (const float*)d_in[4];
    const float* bu   = (const float*)d_in[5];
    const float* ln1g = (const float*)d_in[6];
    const float* ln1b = (const float*)d_in[7];
    const float* ln2g = (const float*)d_in[8];
    const float* ln2b = (const float*)d_in[9];
    const float* W1   = (const float*)d_in[10];
    const float* b1   = (const float*)d_in[11];
    const float* W2   = (const float*)d_in[12];
    const float* b2   = (const float*)d_in[13];
    float* out = (float*)d_out;

    float *Y, *Q, *Kp, *V, *S, *ATT, *X1, *H1;
    cudaGetSymbolAddress((void**)&Y,   g_Y);
    cudaGetSymbolAddress((void**)&Q,   g_Q);
    cudaGetSymbolAddress((void**)&Kp,  g_K);
    cudaGetSymbolAddress((void**)&V,   g_V);
    cudaGetSymbolAddress((void**)&S,   g_S);
    cudaGetSymbolAddress((void**)&ATT, g_ATT);
    cudaGetSymbolAddress((void**)&X1,  g_X1);
    cudaGetSymbolAddress((void**)&H1,  g_H1);

    // split-K partial buffers alias g_S (dead after PV GEMM)
    float* P0 = S;
    float* P1 = S + (size_t)NTOK * D_MODEL;

    cudaFuncSetAttribute(gemm_cp<256,4,false,false,false,false,true >, cudaFuncAttributeMaxDynamicSharedMemorySize, SMEM_NN256);
    cudaFuncSetAttribute(gemm_cp<256,4,true ,false,false,false,false>, cudaFuncAttributeMaxDynamicSharedMemorySize, SMEM_NT256);
    cudaFuncSetAttribute(gemm_cp<256,4,false,true ,true ,false,true >, cudaFuncAttributeMaxDynamicSharedMemorySize, SMEM_NN256);
    cudaFuncSetAttribute(gemm_cp<128,3,false,false,false,false,false>, cudaFuncAttributeMaxDynamicSharedMemorySize, SMEM_NN128);

    const float inv_sqrt_d = 0.03608439182435161f;   // 1/sqrt(768)

    // 0) LN1
    layernorm_kernel<<<NTOK, 256>>>(x, ln1g, ln1b, Y);

    // 1) Q/K/V = Y @ W{q,k,v}  (M=4096, N=9216, K=768) — raw weights (HW tf32 truncation)
    {
        dim3 grid(DH / 256, NTOK / 128, 1);
        gemm_cp<256,4,false,false,false,false,true><<<grid, 256, SMEM_NN256>>>(Y, Wq, nullptr, nullptr, Q,
            D_MODEL, D_MODEL, DH, DH, 0, 1.f, 0,0,0,0,0,0,0,0, 1);
        gemm_cp<256,4,false,false,false,false,true><<<grid, 256, SMEM_NN256>>>(Y, Wk, nullptr, nullptr, Kp,
            D_MODEL, D_MODEL, DH, DH, 0, 1.f, 0,0,0,0,0,0,0,0, 1);
        gemm_cp<256,4,false,false,false,false,true><<<grid, 256, SMEM_NN256>>>(Y, Wv, nullptr, nullptr, V,
            D_MODEL, D_MODEL, DH, DH, 0, 1.f, 0,0,0,0,0,0,0,0, 1);
    }

    // 2) S[b,h] = (Q_bh @ K_bh^T)/sqrt(768)  (M=N=1024, K=768, batch=48; NT)
    {
        dim3 grid(SEQ / 256, SEQ / 128, BATCH * NHEAD);
        gemm_cp<256,4,true,false,false,false,false><<<grid, 256, SMEM_NT256>>>(Q, Kp, nullptr, nullptr, S,
            D_MODEL, DH, DH, SEQ, 0, inv_sqrt_d,
            (ll)SEQ * DH, (ll)D_MODEL,
            (ll)SEQ * DH, (ll)D_MODEL,
            (ll)NHEAD * SEQ * SEQ, (ll)SEQ * SEQ,
            0, 0, NHEAD);
    }

    // 3) softmax (rounds P to tf32)
    softmax_kernel<<<BATCH * NHEAD * SEQ, 256>>>(S);

    // 4) ATT[b,:,h,:] = P_bh @ V_bh  (M=1024, N=768, K=1024, batch=48; NN)
    {
        dim3 grid(D_MODEL / 256, SEQ / 128, BATCH * NHEAD);
        gemm_cp<256,4,false,false,false,false,true><<<grid, 256, SMEM_NN256>>>(S, V, nullptr, nullptr, ATT,
            SEQ, SEQ, DH, DH, 0, 1.f,
            (ll)NHEAD * SEQ * SEQ, (ll)SEQ * SEQ,
            (ll)SEQ * DH, (ll)D_MODEL,
            (ll)SEQ * DH, (ll)D_MODEL,
            0, 0, NHEAD);
    }

    // 5) Wu split-K=2: partials, then X1 = P0 + P1 + bu + x
    {
        dim3 grid(D_MODEL / 128, NTOK / 128, 1);
        gemm_cp<128,3,false,false,false,false,false><<<grid, 128, SMEM_NN128>>>(ATT, Wu,
            nullptr, nullptr, P0, DH/2, DH, D_MODEL, D_MODEL, 0, 1.f, 0,0,0,0,0,0,0,0, 1);
        gemm_cp<128,3,false,false,false,false,false><<<grid, 128, SMEM_NN128>>>(ATT + DH/2, Wu + (ll)(DH/2) * D_MODEL,
            nullptr, nullptr, P1, DH/2, DH, D_MODEL, D_MODEL, 0, 1.f, 0,0,0,0,0,0,0,0, 1);
        const int n4 = NTOK * D_MODEL / 4;
        combine_kernel<<<(n4 + 255) / 256, 256>>>((const float4*)P0, (const float4*)P1, bu,
                                                  (const float4*)x, (float4*)X1, n4);
    }

    // 6) LN2
    layernorm_kernel<<<NTOK, 256>>>(X1, ln2g, ln2b, Y);

    // 7) H1 = relu(Y @ W1 + b1)  (M=4096, N=3072, K=768)
    {
        dim3 grid(DFF / 256, NTOK / 128, 1);
        gemm_cp<256,4,false,true,true,false,true><<<grid, 256, SMEM_NN256>>>(Y, W1, b1, nullptr, H1,
            D_MODEL, D_MODEL, DFF, DFF, 0, 1.f, 0,0,0,0,0,0,0,0, 1);
    }

    // 8) W2 split-K=2: partials, then out = P0 + P1 + b2 + X1
    {
        dim3 grid(D_MODEL / 128, NTOK / 128, 1);
        gemm_cp<128,3,false,false,false,false,false><<<grid, 128, SMEM_NN128>>>(H1, W2,
            nullptr, nullptr, P0, DFF/2, DFF, D_MODEL, D_MODEL, 0, 1.f, 0,0,0,0,0,0,0,0, 1);
        gemm_cp<128,3,false,false,false,false,false><<<grid, 128, SMEM_NN128>>>(H1 + DFF/2, W2 + (ll)(DFF/2) * D_MODEL,
            nullptr, nullptr, P1, DFF/2, DFF, D_MODEL, D_MODEL, 0, 1.f, 0,0,0,0,0,0,0,0, 1);
        const int n4 = NTOK * D_MODEL / 4;
        combine_kernel<<<(n4 + 255) / 256, 256>>>((const float4*)P0, (const float4*)P1, b2,
                                                  (const float4*)X1, (float4*)out, n4);
    }

    (void)in_sizes; (void)n_in; (void)out_size;
}

// round 7
// speedup vs baseline: 1.8346x; 1.0992x over previous
#include <cuda_runtime.h>
#include <cstdint>

#define D_MODEL 768
#define NHEAD   12
#define SEQ     1024
#define BATCH   4
#define NTOK    (BATCH*SEQ)        /* 4096 */
#define DH      (D_MODEL*NHEAD)    /* 9216 */
#define DFF     (4*D_MODEL)        /* 3072 */
#define LN_EPS  1e-5f

typedef long long ll;

// ---------------- scratch (device globals; no allocation allowed) ----------------
__device__ float g_Y  [(size_t)NTOK * D_MODEL];
__device__ float g_Q  [(size_t)NTOK * DH];
__device__ float g_K  [(size_t)NTOK * DH];
__device__ float g_V  [(size_t)NTOK * DH];
__device__ float g_S  [(size_t)BATCH * NHEAD * SEQ * SEQ];   // scores; later aliased as split-K partials
__device__ float g_ATT[(size_t)NTOK * DH];
__device__ float g_X1 [(size_t)NTOK * D_MODEL];
__device__ float g_H1 [(size_t)NTOK * DFF];

// ---------------- helpers ----------------
__device__ __forceinline__ float to_tf32(float x) {
    uint32_t u;
    asm("cvt.rna.tf32.f32 %0, %1;" : "=r"(u) : "f"(x));
    return __uint_as_float(u);
}
__device__ __forceinline__ uint32_t smem_u32(const void* p) {
    uint32_t a;
    asm("{ .reg .u64 t; cvta.to.shared.u64 t, %1; cvt.u32.u64 %0, t; }" : "=r"(a) : "l"(p));
    return a;
}
__device__ __forceinline__ void cp16(uint32_t dst, const void* src) {
    asm volatile("cp.async.cg.shared.global [%0], [%1], 16;" :: "r"(dst), "l"(src) : "memory");
}
__device__ __forceinline__ void cp_commit() {
    asm volatile("cp.async.commit_group;" ::: "memory");
}
template<int N>
__device__ __forceinline__ void cp_wait() {
    asm volatile("cp.async.wait_group %0;" :: "n"(N) : "memory");
}
__device__ __forceinline__ void mma_tf32(float c[4],
                                         uint32_t a0, uint32_t a1, uint32_t a2, uint32_t a3,
                                         uint32_t b0, uint32_t b1) {
    asm("mma.sync.aligned.m16n8k8.row.col.f32.tf32.tf32.f32 "
        "{%0,%1,%2,%3}, {%4,%5,%6,%7}, {%8,%9}, {%0,%1,%2,%3};"
        : "+f"(c[0]), "+f"(c[1]), "+f"(c[2]), "+f"(c[3])
        : "r"(a0), "r"(a1), "r"(a2), "r"(a3), "r"(b0), "r"(b1));
}

// ---------------- tf32 tensor-core GEMM, cp.async multi-stage, warp tile 64x64 ------
// C[m,n] = epi( alpha * sum_k A[m,k] * B(k,n) )
//   BT=false: B is K x N row-major.  BT=true: B is N x K row-major (A @ B^T).
// Tile: 128(M) x TN(N) x KT(K).  TN=256 -> 8 warps (2x4), TN=128 -> 4 warps (2x2).
// Big kernels: KT=64, 2 stages (halved barrier rate vs KT=32).
// Split-K kernels: TN=128, KT=32, 3 stages (2 CTAs/SM).
// smem A: [m][k] pitch KT+4.  B NN: [k][n] pitch TN+8.  B NT: [n][k] pitch KT+4.
// All consumer LDS.32 gathers and cp.async stores are 32-bank conflict-free.
template<int TN, int KT, int STAGES, bool BT, bool RELU, bool HASB, bool HASR, bool ROUND>
__global__ __launch_bounds__(TN == 256 ? 256 : 128, 1)
void gemm_cp(const float* __restrict__ A, const float* __restrict__ B,
             const float* __restrict__ bias, const float* __restrict__ Res,
             float* __restrict__ C,
             int K, int lda, int ldb, int ldc, int ldr, float alpha,
             ll saO, ll saI, ll sbO, ll sbI, ll scO, ll scI, ll srO, ll srI,
             int innerCnt)
{
    constexpr int THREADS = (TN == 256) ? 256 : 128;
    constexpr int PA      = KT + 4;                    // A / B-NT pitch
    constexpr int PB      = TN + 8;                    // B-NN pitch
    constexpr int A_F     = 128 * PA;
    constexpr int B_F     = BT ? TN * PA : KT * PB;
    constexpr int STAGE_F = A_F + B_F;
    constexpr int A_PER   = (128 * KT / 4) / THREADS;  // float4 per thread for A
    constexpr int B_PER   = (TN * KT / 4) / THREADS;
    constexpr int CPR     = KT / 4;                    // float4 chunks per K-row
    constexpr int CPRN    = TN / 4;

    extern __shared__ float dynsm[];

    const int tid  = threadIdx.x;
    const int wid  = tid >> 5;
    const int lane = tid & 31;
    const int g    = lane >> 2;
    const int tig  = lane & 3;
    const int wm   = (TN == 256) ? (wid >> 2) : (wid >> 1);
    const int wn   = (TN == 256) ? (wid & 3)  : (wid & 1);

    const int z  = blockIdx.z;
    const int zo = z / innerCnt;
    const int zi = z - zo * innerCnt;
    A += zo * saO + zi * saI;
    B += zo * sbO + zi * sbI;
    C += zo * scO + zi * scI;
    if (HASR) Res += zo * srO + zi * srI;

    const int m0 = blockIdx.y * 128;
    const int n0 = blockIdx.x * TN;
    A += (ll)m0 * lda;
    B += BT ? (ll)n0 * ldb : (ll)n0;

    const uint32_t smb = smem_u32(dynsm);

    auto issue = [&](int tile) {
        const int stage = tile % STAGES;
        const uint32_t sA = smb + (uint32_t)(stage * STAGE_F) * 4u;
        const uint32_t sB = sA + (uint32_t)A_F * 4u;
        const int k0 = tile * KT;
        #pragma unroll
        for (int i = 0; i < A_PER; i++) {
            const int v = tid + i * THREADS;
            const int m = v / CPR, kc = (v % CPR) * 4;
            cp16(sA + (uint32_t)(m * PA + kc) * 4u, A + (ll)m * lda + k0 + kc);
        }
        #pragma unroll
        for (int i = 0; i < B_PER; i++) {
            const int v = tid + i * THREADS;
            if (BT) {
                const int n = v / CPR, kc = (v % CPR) * 4;
                cp16(sB + (uint32_t)(n * PA + kc) * 4u, B + (ll)n * ldb + k0 + kc);
            } else {
                const int k = v / CPRN, nc = (v % CPRN) * 4;
                cp16(sB + (uint32_t)(k * PB + nc) * 4u, B + (ll)(k0 + k) * ldb + nc);
            }
        }
        cp_commit();
    };

    float acc[4][8][4];
    #pragma unroll
    for (int mt = 0; mt < 4; mt++)
        #pragma unroll
        for (int nt = 0; nt < 8; nt++)
            #pragma unroll
            for (int r = 0; r < 4; r++) acc[mt][nt][r] = 0.f;

    const int T = K / KT;
    #pragma unroll
    for (int s = 0; s < STAGES - 1; s++) issue(s);

    for (int it = 0; it < T; ++it) {
        cp_wait<STAGES - 2>();
        __syncthreads();
        if (it + STAGES - 1 < T) issue(it + STAGES - 1);

        const float* As  = dynsm + (it % STAGES) * STAGE_F;
        const float* Bsm = As + A_F;

        #pragma unroll
        for (int ksi = 0; ksi < KT / 8; ksi++) {
            const int kk = ksi * 8 + tig;
            uint32_t a[4][4], b[8][2];
            #pragma unroll
            for (int mt = 0; mt < 4; mt++) {
                const int mA = wm * 64 + mt * 16 + g;
                a[mt][0] = __float_as_uint(As[(mA    ) * PA + kk    ]);
                a[mt][1] = __float_as_uint(As[(mA + 8) * PA + kk    ]);
                a[mt][2] = __float_as_uint(As[(mA    ) * PA + kk + 4]);
                a[mt][3] = __float_as_uint(As[(mA + 8) * PA + kk + 4]);
            }
            #pragma unroll
            for (int nt = 0; nt < 8; nt++) {
                const int nB = wn * 64 + nt * 8 + g;
                if (BT) {
                    b[nt][0] = __float_as_uint(Bsm[nB * PA + kk    ]);
                    b[nt][1] = __float_as_uint(Bsm[nB * PA + kk + 4]);
                } else {
                    b[nt][0] = __float_as_uint(Bsm[(kk    ) * PB + nB]);
                    b[nt][1] = __float_as_uint(Bsm[(kk + 4) * PB + nB]);
                }
            }
            #pragma unroll
            for (int mt = 0; mt < 4; mt++)
                #pragma unroll
                for (int nt = 0; nt < 8; nt++)
                    mma_tf32(acc[mt][nt], a[mt][0], a[mt][1], a[mt][2], a[mt][3],
                             b[nt][0], b[nt][1]);
        }
    }

    // ---- epilogue ----
    #pragma unroll
    for (int mt = 0; mt < 4; mt++) {
        #pragma unroll
        for (int nt = 0; nt < 8; nt++) {
            const int n = n0 + wn * 64 + nt * 8 + tig * 2;
            float bv0 = 0.f, bv1 = 0.f;
            if (HASB) { bv0 = bias[n]; bv1 = bias[n + 1]; }
            #pragma unroll
            for (int h = 0; h < 2; h++) {
                const int m = m0 + wm * 64 + mt * 16 + g + h * 8;
                float x0 = alpha * acc[mt][nt][h * 2 + 0] + bv0;
                float x1 = alpha * acc[mt][nt][h * 2 + 1] + bv1;
                if (RELU) { x0 = fmaxf(x0, 0.f); x1 = fmaxf(x1, 0.f); }
                if (HASR) {
                    x0 += Res[(ll)m * ldr + n];
                    x1 += Res[(ll)m * ldr + n + 1];
                }
                if (ROUND) { x0 = to_tf32(x0); x1 = to_tf32(x1); }
                float2 w; w.x = x0; w.y = x1;
                *reinterpret_cast<float2*>(C + (ll)m * ldc + n) = w;
            }
        }
    }
}

// ---------------- split-K combine (3-way): out = P0 + P1 + P2 + bias + res ----------
__global__ void combine3_kernel(const float4* __restrict__ P0, const float4* __restrict__ P1,
                                const float4* __restrict__ P2,
                                const float* __restrict__ bias, const float4* __restrict__ res,
                                float4* __restrict__ out, int n4)
{
    const int i = blockIdx.x * blockDim.x + threadIdx.x;
    if (i >= n4) return;
    const int c = (i % (D_MODEL / 4)) * 4;
    const float4 p = P0[i], q = P1[i], s = P2[i], r = res[i];
    float4 o;
    o.x = p.x + q.x + s.x + bias[c + 0] + r.x;
    o.y = p.y + q.y + s.y + bias[c + 1] + r.y;
    o.z = p.z + q.z + s.z + bias[c + 2] + r.z;
    o.w = p.w + q.w + s.w + bias[c + 3] + r.w;
    out[i] = o;
}

// ---------------- layernorm (rounds output to tf32: it feeds GEMM A) ----------------
__global__ void layernorm_kernel(const float* __restrict__ x,
                                 const float* __restrict__ gm,
                                 const float* __restrict__ bt,
                                 float* __restrict__ y)
{
    const ll base = (ll)blockIdx.x * D_MODEL;
    const int t = threadIdx.x;
    float v[3];
    float lsum = 0.f, lsq = 0.f;
    #pragma unroll
    for (int i = 0; i < 3; i++) {
        v[i] = x[base + t + i * 256];
        lsum += v[i];
        lsq  += v[i] * v[i];
    }
    __shared__ float sh[16];
    #pragma unroll
    for (int o = 16; o; o >>= 1) {
        lsum += __shfl_xor_sync(0xffffffffu, lsum, o);
        lsq  += __shfl_xor_sync(0xffffffffu, lsq,  o);
    }
    const int wid = t >> 5, lane = t & 31;
    if (lane == 0) { sh[wid] = lsum; sh[8 + wid] = lsq; }
    __syncthreads();
    if (wid == 0) {
        float a = (lane < 8) ? sh[lane] : 0.f;
        float b = (lane < 8) ? sh[8 + lane] : 0.f;
        #pragma unroll
        for (int o = 4; o; o >>= 1) {
            a += __shfl_xor_sync(0xffffffffu, a, o);
            b += __shfl_xor_sync(0xffffffffu, b, o);
        }
        if (lane == 0) { sh[0] = a; sh[1] = b; }
    }
    __syncthreads();
    const float mu   = sh[0] * (1.f / D_MODEL);
    const float var  = sh[1] * (1.f / D_MODEL) - mu * mu;
    const float rstd = rsqrtf(var + LN_EPS);
    #pragma unroll
    for (int i = 0; i < 3; i++) {
        const int idx = t + i * 256;
        y[base + idx] = to_tf32((v[i] - mu) * rstd * gm[idx] + bt[idx]);
    }
}

// ---------------- row softmax over length-1024 rows (rounds output to tf32) --------
__global__ void softmax_kernel(float* __restrict__ S)
{
    float* p = S + (ll)blockIdx.x * SEQ;
    const int t = threadIdx.x;
    const int wid = t >> 5, lane = t & 31;
    __shared__ float sh[8];

    float v[4];
    float mx = -3.4e38f;
    #pragma unroll
    for (int i = 0; i < 4; i++) { v[i] = p[t + i * 256]; mx = fmaxf(mx, v[i]); }
    #pragma unroll
    for (int o = 16; o; o >>= 1) mx = fmaxf(mx, __shfl_xor_sync(0xffffffffu, mx, o));
    if (lane == 0) sh[wid] = mx;
    __syncthreads();
    if (wid == 0) {
        float a = (lane < 8) ? sh[lane] : -3.4e38f;
        #pragma unroll
        for (int o = 4; o; o >>= 1) a = fmaxf(a, __shfl_xor_sync(0xffffffffu, a, o));
        if (lane == 0) sh[0] = a;
    }
    __syncthreads();
    mx = sh[0];
    __syncthreads();

    float s = 0.f;
    #pragma unroll
    for (int i = 0; i < 4; i++) { v[i] = __expf(v[i] - mx); s += v[i]; }
    #pragma unroll
    for (int o = 16; o; o >>= 1) s += __shfl_xor_sync(0xffffffffu, s, o);
    if (lane == 0) sh[wid] = s;
    __syncthreads();
    if (wid == 0) {
        float a = (lane < 8) ? sh[lane] : 0.f;
        #pragma unroll
        for (int o = 4; o; o >>= 1) a += __shfl_xor_sync(0xffffffffu, a, o);
        if (lane == 0) sh[0] = a;
    }
    __syncthreads();
    const float inv = 1.f / sh[0];
    #pragma unroll
    for (int i = 0; i < 4; i++) p[t + i * 256] = to_tf32(v[i] * inv);
}

// ---------------- launch ----------------
// smem bytes = STAGE_F * STAGES * 4
#define SMEM_NN256 204800   /* (128*68 + 64*264)*2st*4B */
#define SMEM_NT256 208896   /* (128*68 + 256*68)*2st*4B */
#define SMEM_NN128 107520   /* (128*36 + 32*136)*3st*4B -> 2 CTAs/SM */

extern "C" void kernel_launch(void* const* d_in, const int* in_sizes, int n_in,
                              void* d_out, int out_size)
{
    const float* x    = (const float*)d_in[0];
    const float* Wq   = (const float*)d_in[1];
    const float* Wk   = (const float*)d_in[2];
    const float* Wv   = (const float*)d_in[3];
    const float* Wu   = (const float*)d_in[4];
    const float* bu   = (const float*)d_in[5];
    const float* ln1g = (const float*)d_in[6];
    const float* ln1b = (const float*)d_in[7];
    const float* ln2g = (const float*)d_in[8];
    const float* ln2b = (const float*)d_in[9];
    const float* W1   = (const float*)d_in[10];
    const float* b1   = (const float*)d_in[11];
    const float* W2   = (const float*)d_in[12];
    const float* b2   = (const float*)d_in[13];
    float* out = (float*)d_out;

    float *Y, *Q, *Kp, *V, *S, *ATT, *X1, *H1;
    cudaGetSymbolAddress((void**)&Y,   g_Y);
    cudaGetSymbolAddress((void**)&Q,   g_Q);
    cudaGetSymbolAddress((void**)&Kp,  g_K);
    cudaGetSymbolAddress((void**)&V,   g_V);
    cudaGetSymbolAddress((void**)&S,   g_S);
    cudaGetSymbolAddress((void**)&ATT, g_ATT);
    cudaGetSymbolAddress((void**)&X1,  g_X1);
    cudaGetSymbolAddress((void**)&H1,  g_H1);

    // split-K partial buffers alias g_S (dead after PV GEMM)
    float* P0 = S;
    float* P1 = S + (size_t)NTOK * D_MODEL;
    float* P2 = S + (size_t)2 * NTOK * D_MODEL;

    cudaFuncSetAttribute(gemm_cp<256,64,2,false,false,false,false,true >, cudaFuncAttributeMaxDynamicSharedMemorySize, SMEM_NN256);
    cudaFuncSetAttribute(gemm_cp<256,64,2,true ,false,false,false,false>, cudaFuncAttributeMaxDynamicSharedMemorySize, SMEM_NT256);
    cudaFuncSetAttribute(gemm_cp<256,64,2,false,true ,true ,false,true >, cudaFuncAttributeMaxDynamicSharedMemorySize, SMEM_NN256);
    cudaFuncSetAttribute(gemm_cp<128,32,3,false,false,false,false,false>, cudaFuncAttributeMaxDynamicSharedMemorySize, SMEM_NN128);

    const float inv_sqrt_d = 0.03608439182435161f;   // 1/sqrt(768)

    // 0) LN1
    layernorm_kernel<<<NTOK, 256>>>(x, ln1g, ln1b, Y);

    // 1) Q/K/V = Y @ W{q,k,v}  (M=4096, N=9216, K=768)
    {
        dim3 grid(DH / 256, NTOK / 128, 1);
        gemm_cp<256,64,2,false,false,false,false,true><<<grid, 256, SMEM_NN256>>>(Y, Wq, nullptr, nullptr, Q,
            D_MODEL, D_MODEL, DH, DH, 0, 1.f, 0,0,0,0,0,0,0,0, 1);
        gemm_cp<256,64,2,false,false,false,false,true><<<grid, 256, SMEM_NN256>>>(Y, Wk, nullptr, nullptr, Kp,
            D_MODEL, D_MODEL, DH, DH, 0, 1.f, 0,0,0,0,0,0,0,0, 1);
        gemm_cp<256,64,2,false,false,false,false,true><<<grid, 256, SMEM_NN256>>>(Y, Wv, nullptr, nullptr, V,
            D_MODEL, D_MODEL, DH, DH, 0, 1.f, 0,0,0,0,0,0,0,0, 1);
    }

    // 2) S[b,h] = (Q_bh @ K_bh^T)/sqrt(768)  (M=N=1024, K=768, batch=48; NT)
    {
        dim3 grid(SEQ / 256, SEQ / 128, BATCH * NHEAD);
        gemm_cp<256,64,2,true,false,false,false,false><<<grid, 256, SMEM_NT256>>>(Q, Kp, nullptr, nullptr, S,
            D_MODEL, DH, DH, SEQ, 0, inv_sqrt_d,
            (ll)SEQ * DH, (ll)D_MODEL,
            (ll)SEQ * DH, (ll)D_MODEL,
            (ll)NHEAD * SEQ * SEQ, (ll)SEQ * SEQ,
            0, 0, NHEAD);
    }

    // 3) softmax (rounds P to tf32)
    softmax_kernel<<<BATCH * NHEAD * SEQ, 256>>>(S);

    // 4) ATT[b,:,h,:] = P_bh @ V_bh  (M=1024, N=768, K=1024, batch=48; NN)
    {
        dim3 grid(D_MODEL / 256, SEQ / 128, BATCH * NHEAD);
        gemm_cp<256,64,2,false,false,false,false,true><<<grid, 256, SMEM_NN256>>>(S, V, nullptr, nullptr, ATT,
            SEQ, SEQ, DH, DH, 0, 1.f,
            (ll)NHEAD * SEQ * SEQ, (ll)SEQ * SEQ,
            (ll)SEQ * DH, (ll)D_MODEL,
            (ll)SEQ * DH, (ll)D_MODEL,
            0, 0, NHEAD);
    }

    // 5) Wu split-K=3: partials (batched via z), then X1 = P0+P1+P2 + bu + x
    {
        dim3 grid(D_MODEL / 128, NTOK / 128, 3);
        gemm_cp<128,32,3,false,false,false,false,false><<<grid, 128, SMEM_NN128>>>(ATT, Wu,
            nullptr, nullptr, P0, DH/3, DH, D_MODEL, D_MODEL, 0, 1.f,
            0, (ll)(DH/3),                       // A: k-slab offset per z
            0, (ll)(DH/3) * D_MODEL,             // B: k-slab offset per z
            0, (ll)NTOK * D_MODEL,               // C: partial buffer per z
            0, 0, 3);
        const int n4 = NTOK * D_MODEL / 4;
        combine3_kernel<<<(n4 + 255) / 256, 256>>>((const float4*)P0, (const float4*)P1,
                                                   (const float4*)P2, bu,
                                                   (const float4*)x, (float4*)X1, n4);
    }

    // 6) LN2
    layernorm_kernel<<<NTOK, 256>>>(X1, ln2g, ln2b, Y);

    // 7) H1 = relu(Y @ W1 + b1)  (M=4096, N=3072, K=768)
    {
        dim3 grid(DFF / 256, NTOK / 128, 1);
        gemm_cp<256,64,2,false,true,true,false,true><<<grid, 256, SMEM_NN256>>>(Y, W1, b1, nullptr, H1,
            D_MODEL, D_MODEL, DFF, DFF, 0, 1.f, 0,0,0,0,0,0,0,0, 1);
    }

    // 8) W2 split-K=3: partials, then out = P0+P1+P2 + b2 + X1
    {
        dim3 grid(D_MODEL / 128, NTOK / 128, 3);
        gemm_cp<128,32,3,false,false,false,false,false><<<grid, 128, SMEM_NN128>>>(H1, W2,
            nullptr, nullptr, P0, DFF/3, DFF, D_MODEL, D_MODEL, 0, 1.f,
            0, (ll)(DFF/3),
            0, (ll)(DFF/3) * D_MODEL,
            0, (ll)NTOK * D_MODEL,
            0, 0, 3);
        const int n4 = NTOK * D_MODEL / 4;
        combine3_kernel<<<(n4 + 255) / 256, 256>>>((const float4*)P0, (const float4*)P1,
                                                   (const float4*)P2, b2,
                                                   (const float4*)X1, (float4*)out, n4);
    }

    (void)in_sizes; (void)n_in; (void)out_size;
}

// round 8
// speedup vs baseline: 1.9028x; 1.0372x over previous
#include <cuda_runtime.h>
#include <cstdint>

#define D_MODEL 768
#define NHEAD   12
#define SEQ     1024
#define BATCH   4
#define NTOK    (BATCH*SEQ)        /* 4096 */
#define DH      (D_MODEL*NHEAD)    /* 9216 */
#define DFF     (4*D_MODEL)        /* 3072 */
#define LN_EPS  1e-5f

typedef long long ll;

// ---------------- scratch (device globals; no allocation allowed) ----------------
__device__ float g_Y  [(size_t)NTOK * D_MODEL];
__device__ float g_Q  [(size_t)NTOK * DH];
__device__ float g_K  [(size_t)NTOK * DH];
__device__ float g_V  [(size_t)NTOK * DH];
__device__ float g_S  [(size_t)BATCH * NHEAD * SEQ * SEQ];   // scores; later aliased as split-K partials
__device__ float g_ATT[(size_t)NTOK * DH];
__device__ float g_X1 [(size_t)NTOK * D_MODEL];
__device__ float g_H1 [(size_t)NTOK * DFF];

// ---------------- helpers ----------------
__device__ __forceinline__ float to_tf32(float x) {
    uint32_t u;
    asm("cvt.rna.tf32.f32 %0, %1;" : "=r"(u) : "f"(x));
    return __uint_as_float(u);
}
__device__ __forceinline__ uint32_t smem_u32(const void* p) {
    uint32_t a;
    asm("{ .reg .u64 t; cvta.to.shared.u64 t, %1; cvt.u32.u64 %0, t; }" : "=r"(a) : "l"(p));
    return a;
}
__device__ __forceinline__ void cp16(uint32_t dst, const void* src) {
    asm volatile("cp.async.cg.shared.global [%0], [%1], 16;" :: "r"(dst), "l"(src) : "memory");
}
__device__ __forceinline__ void cp_commit() {
    asm volatile("cp.async.commit_group;" ::: "memory");
}
template<int N>
__device__ __forceinline__ void cp_wait() {
    asm volatile("cp.async.wait_group %0;" :: "n"(N) : "memory");
}
__device__ __forceinline__ void mma_tf32(float c[4],
                                         uint32_t a0, uint32_t a1, uint32_t a2, uint32_t a3,
                                         uint32_t b0, uint32_t b1) {
    asm("mma.sync.aligned.m16n8k8.row.col.f32.tf32.tf32.f32 "
        "{%0,%1,%2,%3}, {%4,%5,%6,%7}, {%8,%9}, {%0,%1,%2,%3};"
        : "+f"(c[0]), "+f"(c[1]), "+f"(c[2]), "+f"(c[3])
        : "r"(a0), "r"(a1), "r"(a2), "r"(a3), "r"(b0), "r"(b1));
}

// ---------------- tf32 tensor-core GEMM, cp.async 3-stage, 2 CTAs/SM ---------------
// C[m,n] = epi( alpha * sum_k A[m,k] * B(k,n) )
//   BT=false: B is K x N row-major.  BT=true: B is N x K row-major (A @ B^T).
// CTA tile 128x128x32, 128 threads (4 warps, 2x2), warp tile 64x64.
// smem/CTA: NN 107.5KB, NT 110.6KB -> 2 CTAs per SM (regs 255*256 <= 64K RF).
// The co-resident CTA fills LDS-latency / barrier / prolog-epilog gaps.
// smem A: [m][k] pitch 36.  B NN: [k][n] pitch 136.  B NT: [n][k] pitch 36.
// All LDS gathers and cp.async stores are 32-bank conflict-free.
template<bool BT, bool RELU, bool HASB, bool HASR, bool ROUND>
__global__ __launch_bounds__(128, 2)
void gemm_cp(const float* __restrict__ A, const float* __restrict__ B,
             const float* __restrict__ bias, const float* __restrict__ Res,
             float* __restrict__ C,
             int K, int lda, int ldb, int ldc, int ldr, float alpha,
             ll saO, ll saI, ll sbO, ll sbI, ll scO, ll scI, ll srO, ll srI,
             int innerCnt)
{
    constexpr int STAGES  = 3;
    constexpr int PA      = 36;                  // A / B-NT pitch
    constexpr int PB      = 136;                 // B-NN pitch
    constexpr int A_F     = 128 * PA;            // 4608 floats
    constexpr int B_F     = BT ? 128 * PA : 32 * PB;
    constexpr int STAGE_F = A_F + B_F;

    extern __shared__ float dynsm[];

    const int tid  = threadIdx.x;
    const int wid  = tid >> 5;
    const int lane = tid & 31;
    const int g    = lane >> 2;
    const int tig  = lane & 3;
    const int wm   = wid >> 1;                   // 0..1
    const int wn   = wid & 1;                    // 0..1

    const int z  = blockIdx.z;
    const int zo = z / innerCnt;
    const int zi = z - zo * innerCnt;
    A += zo * saO + zi * saI;
    B += zo * sbO + zi * sbI;
    C += zo * scO + zi * scI;
    if (HASR) Res += zo * srO + zi * srI;

    const int m0 = blockIdx.y * 128;
    const int n0 = blockIdx.x * 128;
    A += (ll)m0 * lda;
    B += BT ? (ll)n0 * ldb : (ll)n0;

    const uint32_t smb = smem_u32(dynsm);

    auto issue = [&](int tile) {
        const int stage = tile % STAGES;
        const uint32_t sA = smb + (uint32_t)(stage * STAGE_F) * 4u;
        const uint32_t sB = sA + (uint32_t)A_F * 4u;
        const int k0 = tile * 32;
        #pragma unroll
        for (int i = 0; i < 8; i++) {            // A: 128 rows x 32 k, 8 float4/thread
            const int v = tid + i * 128;
            const int m = v >> 3, kc = (v & 7) * 4;
            cp16(sA + (uint32_t)(m * PA + kc) * 4u, A + (ll)m * lda + k0 + kc);
        }
        #pragma unroll
        for (int i = 0; i < 8; i++) {            // B: 128x32 (either orientation)
            const int v = tid + i * 128;
            if (BT) {
                const int n = v >> 3, kc = (v & 7) * 4;
                cp16(sB + (uint32_t)(n * PA + kc) * 4u, B + (ll)n * ldb + k0 + kc);
            } else {
                const int k = v >> 5, nc = (v & 31) * 4;
                cp16(sB + (uint32_t)(k * PB + nc) * 4u, B + (ll)(k0 + k) * ldb + nc);
            }
        }
        cp_commit();
    };

    float acc[4][8][4];
    #pragma unroll
    for (int mt = 0; mt < 4; mt++)
        #pragma unroll
        for (int nt = 0; nt < 8; nt++)
            #pragma unroll
            for (int r = 0; r < 4; r++) acc[mt][nt][r] = 0.f;

    const int T = K >> 5;
    issue(0); issue(1);

    for (int it = 0; it < T; ++it) {
        cp_wait<1>();
        __syncthreads();
        if (it + 2 < T) issue(it + 2);

        const float* As  = dynsm + (it % STAGES) * STAGE_F;
        const float* Bsm = As + A_F;

        #pragma unroll
        for (int ksi = 0; ksi < 4; ksi++) {
            const int kk = ksi * 8 + tig;
            uint32_t a[4][4], b[8][2];
            #pragma unroll
            for (int mt = 0; mt < 4; mt++) {
                const int mA = wm * 64 + mt * 16 + g;
                a[mt][0] = __float_as_uint(As[(mA    ) * PA + kk    ]);
                a[mt][1] = __float_as_uint(As[(mA + 8) * PA + kk    ]);
                a[mt][2] = __float_as_uint(As[(mA    ) * PA + kk + 4]);
                a[mt][3] = __float_as_uint(As[(mA + 8) * PA + kk + 4]);
            }
            #pragma unroll
            for (int nt = 0; nt < 8; nt++) {
                const int nB = wn * 64 + nt * 8 + g;
                if (BT) {
                    b[nt][0] = __float_as_uint(Bsm[nB * PA + kk    ]);
                    b[nt][1] = __float_as_uint(Bsm[nB * PA + kk + 4]);
                } else {
                    b[nt][0] = __float_as_uint(Bsm[(kk    ) * PB + nB]);
                    b[nt][1] = __float_as_uint(Bsm[(kk + 4) * PB + nB]);
                }
            }
            #pragma unroll
            for (int mt = 0; mt < 4; mt++)
                #pragma unroll
                for (int nt = 0; nt < 8; nt++)
                    mma_tf32(acc[mt][nt], a[mt][0], a[mt][1], a[mt][2], a[mt][3],
                             b[nt][0], b[nt][1]);
        }
    }

    // ---- epilogue ----
    #pragma unroll
    for (int mt = 0; mt < 4; mt++) {
        #pragma unroll
        for (int nt = 0; nt < 8; nt++) {
            const int n = n0 + wn * 64 + nt * 8 + tig * 2;
            float bv0 = 0.f, bv1 = 0.f;
            if (HASB) { bv0 = bias[n]; bv1 = bias[n + 1]; }
            #pragma unroll
            for (int h = 0; h < 2; h++) {
                const int m = m0 + wm * 64 + mt * 16 + g + h * 8;
                float x0 = alpha * acc[mt][nt][h * 2 + 0] + bv0;
                float x1 = alpha * acc[mt][nt][h * 2 + 1] + bv1;
                if (RELU) { x0 = fmaxf(x0, 0.f); x1 = fmaxf(x1, 0.f); }
                if (HASR) {
                    x0 += Res[(ll)m * ldr + n];
                    x1 += Res[(ll)m * ldr + n + 1];
                }
                if (ROUND) { x0 = to_tf32(x0); x1 = to_tf32(x1); }
                float2 w; w.x = x0; w.y = x1;
                *reinterpret_cast<float2*>(C + (ll)m * ldc + n) = w;
            }
        }
    }
}

// ---------------- split-K combine (3-way): out = P0 + P1 + P2 + bias + res ----------
__global__ void combine3_kernel(const float4* __restrict__ P0, const float4* __restrict__ P1,
                                const float4* __restrict__ P2,
                                const float* __restrict__ bias, const float4* __restrict__ res,
                                float4* __restrict__ out, int n4)
{
    const int i = blockIdx.x * blockDim.x + threadIdx.x;
    if (i >= n4) return;
    const int c = (i % (D_MODEL / 4)) * 4;
    const float4 p = P0[i], q = P1[i], s = P2[i], r = res[i];
    float4 o;
    o.x = p.x + q.x + s.x + bias[c + 0] + r.x;
    o.y = p.y + q.y + s.y + bias[c + 1] + r.y;
    o.z = p.z + q.z + s.z + bias[c + 2] + r.z;
    o.w = p.w + q.w + s.w + bias[c + 3] + r.w;
    out[i] = o;
}

// ---------------- layernorm (rounds output to tf32: it feeds GEMM A) ----------------
__global__ void layernorm_kernel(const float* __restrict__ x,
                                 const float* __restrict__ gm,
                                 const float* __restrict__ bt,
                                 float* __restrict__ y)
{
    const ll base = (ll)blockIdx.x * D_MODEL;
    const int t = threadIdx.x;
    float v[3];
    float lsum = 0.f, lsq = 0.f;
    #pragma unroll
    for (int i = 0; i < 3; i++) {
        v[i] = x[base + t + i * 256];
        lsum += v[i];
        lsq  += v[i] * v[i];
    }
    __shared__ float sh[16];
    #pragma unroll
    for (int o = 16; o; o >>= 1) {
        lsum += __shfl_xor_sync(0xffffffffu, lsum, o);
        lsq  += __shfl_xor_sync(0xffffffffu, lsq,  o);
    }
    const int wid = t >> 5, lane = t & 31;
    if (lane == 0) { sh[wid] = lsum; sh[8 + wid] = lsq; }
    __syncthreads();
    if (wid == 0) {
        float a = (lane < 8) ? sh[lane] : 0.f;
        float b = (lane < 8) ? sh[8 + lane] : 0.f;
        #pragma unroll
        for (int o = 4; o; o >>= 1) {
            a += __shfl_xor_sync(0xffffffffu, a, o);
            b += __shfl_xor_sync(0xffffffffu, b, o);
        }
        if (lane == 0) { sh[0] = a; sh[1] = b; }
    }
    __syncthreads();
    const float mu   = sh[0] * (1.f / D_MODEL);
    const float var  = sh[1] * (1.f / D_MODEL) - mu * mu;
    const float rstd = rsqrtf(var + LN_EPS);
    #pragma unroll
    for (int i = 0; i < 3; i++) {
        const int idx = t + i * 256;
        y[base + idx] = to_tf32((v[i] - mu) * rstd * gm[idx] + bt[idx]);
    }
}

// ---------------- row softmax over length-1024 rows (rounds output to tf32) --------
__global__ void softmax_kernel(float* __restrict__ S)
{
    float* p = S + (ll)blockIdx.x * SEQ;
    const int t = threadIdx.x;
    const int wid = t >> 5, lane = t & 31;
    __shared__ float sh[8];

    float v[4];
    float mx = -3.4e38f;
    #pragma unroll
    for (int i = 0; i < 4; i++) { v[i] = p[t + i * 256]; mx = fmaxf(mx, v[i]); }
    #pragma unroll
    for (int o = 16; o; o >>= 1) mx = fmaxf(mx, __shfl_xor_sync(0xffffffffu, mx, o));
    if (lane == 0) sh[wid] = mx;
    __syncthreads();
    if (wid == 0) {
        float a = (lane < 8) ? sh[lane] : -3.4e38f;
        #pragma unroll
        for (int o = 4; o; o >>= 1) a = fmaxf(a, __shfl_xor_sync(0xffffffffu, a, o));
        if (lane == 0) sh[0] = a;
    }
    __syncthreads();
    mx = sh[0];
    __syncthreads();

    float s = 0.f;
    #pragma unroll
    for (int i = 0; i < 4; i++) { v[i] = __expf(v[i] - mx); s += v[i]; }
    #pragma unroll
    for (int o = 16; o; o >>= 1) s += __shfl_xor_sync(0xffffffffu, s, o);
    if (lane == 0) sh[wid] = s;
    __syncthreads();
    if (wid == 0) {
        float a = (lane < 8) ? sh[lane] : 0.f;
        #pragma unroll
        for (int o = 4; o; o >>= 1) a += __shfl_xor_sync(0xffffffffu, a, o);
        if (lane == 0) sh[0] = a;
    }
    __syncthreads();
    const float inv = 1.f / sh[0];
    #pragma unroll
    for (int i = 0; i < 4; i++) p[t + i * 256] = to_tf32(v[i] * inv);
}

// ---------------- launch ----------------
#define SMEM_NN 107520   /* (128*36 + 32*136)*3st*4B */
#define SMEM_NT 110592   /* (128*36 + 128*36)*3st*4B */

extern "C" void kernel_launch(void* const* d_in, const int* in_sizes, int n_in,
                              void* d_out, int out_size)
{
    const float* x    = (const float*)d_in[0];
    const float* Wq   = (const float*)d_in[1];
    const float* Wk   = (const float*)d_in[2];
    const float* Wv   = (const float*)d_in[3];
    const float* Wu   = (const float*)d_in[4];
    const float* bu   = (const float*)d_in[5];
    const float* ln1g = (const float*)d_in[6];
    const float* ln1b = (const float*)d_in[7];
    const float* ln2g = (const float*)d_in[8];
    const float* ln2b = (const float*)d_in[9];
    const float* W1   = (const float*)d_in[10];
    const float* b1   = (const float*)d_in[11];
    const float* W2   = (const float*)d_in[12];
    const float* b2   = (const float*)d_in[13];
    float* out = (float*)d_out;

    float *Y, *Q, *Kp, *V, *S, *ATT, *X1, *H1;
    cudaGetSymbolAddress((void**)&Y,   g_Y);
    cudaGetSymbolAddress((void**)&Q,   g_Q);
    cudaGetSymbolAddress((void**)&Kp,  g_K);
    cudaGetSymbolAddress((void**)&V,   g_V);
    cudaGetSymbolAddress((void**)&S,   g_S);
    cudaGetSymbolAddress((void**)&ATT, g_ATT);
    cudaGetSymbolAddress((void**)&X1,  g_X1);
    cudaGetSymbolAddress((void**)&H1,  g_H1);

    // split-K partial buffers alias g_S (dead after PV GEMM)
    float* P0 = S;
    float* P1 = S + (size_t)NTOK * D_MODEL;
    float* P2 = S + (size_t)2 * NTOK * D_MODEL;

    cudaFuncSetAttribute(gemm_cp<false,false,false,false,true >, cudaFuncAttributeMaxDynamicSharedMemorySize, SMEM_NN);
    cudaFuncSetAttribute(gemm_cp<true ,false,false,false,false>, cudaFuncAttributeMaxDynamicSharedMemorySize, SMEM_NT);
    cudaFuncSetAttribute(gemm_cp<false,true ,true ,false,true >, cudaFuncAttributeMaxDynamicSharedMemorySize, SMEM_NN);
    cudaFuncSetAttribute(gemm_cp<false,false,false,false,false>, cudaFuncAttributeMaxDynamicSharedMemorySize, SMEM_NN);

    const float inv_sqrt_d = 0.03608439182435161f;   // 1/sqrt(768)

    // 0) LN1
    layernorm_kernel<<<NTOK, 256>>>(x, ln1g, ln1b, Y);

    // 1) Q/K/V = Y @ W{q,k,v}  (M=4096, N=9216, K=768)
    {
        dim3 grid(DH / 128, NTOK / 128, 1);
        gemm_cp<false,false,false,false,true><<<grid, 128, SMEM_NN>>>(Y, Wq, nullptr, nullptr, Q,
            D_MODEL, D_MODEL, DH, DH, 0, 1.f, 0,0,0,0,0,0,0,0, 1);
        gemm_cp<false,false,false,false,true><<<grid, 128, SMEM_NN>>>(Y, Wk, nullptr, nullptr, Kp,
            D_MODEL, D_MODEL, DH, DH, 0, 1.f, 0,0,0,0,0,0,0,0, 1);
        gemm_cp<false,false,false,false,true><<<grid, 128, SMEM_NN>>>(Y, Wv, nullptr, nullptr, V,
            D_MODEL, D_MODEL, DH, DH, 0, 1.f, 0,0,0,0,0,0,0,0, 1);
    }

    // 2) S[b,h] = (Q_bh @ K_bh^T)/sqrt(768)  (M=N=1024, K=768, batch=48; NT)
    {
        dim3 grid(SEQ / 128, SEQ / 128, BATCH * NHEAD);
        gemm_cp<true,false,false,false,false><<<grid, 128, SMEM_NT>>>(Q, Kp, nullptr, nullptr, S,
            D_MODEL, DH, DH, SEQ, 0, inv_sqrt_d,
            (ll)SEQ * DH, (ll)D_MODEL,
            (ll)SEQ * DH, (ll)D_MODEL,
            (ll)NHEAD * SEQ * SEQ, (ll)SEQ * SEQ,
            0, 0, NHEAD);
    }

    // 3) softmax (rounds P to tf32)
    softmax_kernel<<<BATCH * NHEAD * SEQ, 256>>>(S);

    // 4) ATT[b,:,h,:] = P_bh @ V_bh  (M=1024, N=768, K=1024, batch=48; NN)
    {
        dim3 grid(D_MODEL / 128, SEQ / 128, BATCH * NHEAD);
        gemm_cp<false,false,false,false,true><<<grid, 128, SMEM_NN>>>(S, V, nullptr, nullptr, ATT,
            SEQ, SEQ, DH, DH, 0, 1.f,
            (ll)NHEAD * SEQ * SEQ, (ll)SEQ * SEQ,
            (ll)SEQ * DH, (ll)D_MODEL,
            (ll)SEQ * DH, (ll)D_MODEL,
            0, 0, NHEAD);
    }

    // 5) Wu split-K=3: partials (batched via z), then X1 = P0+P1+P2 + bu + x
    {
        dim3 grid(D_MODEL / 128, NTOK / 128, 3);
        gemm_cp<false,false,false,false,false><<<grid, 128, SMEM_NN>>>(ATT, Wu,
            nullptr, nullptr, P0, DH/3, DH, D_MODEL, D_MODEL, 0, 1.f,
            0, (ll)(DH/3),
            0, (ll)(DH/3) * D_MODEL,
            0, (ll)NTOK * D_MODEL,
            0, 0, 3);
        const int n4 = NTOK * D_MODEL / 4;
        combine3_kernel<<<(n4 + 255) / 256, 256>>>((const float4*)P0, (const float4*)P1,
                                                   (const float4*)P2, bu,
                                                   (const float4*)x, (float4*)X1, n4);
    }

    // 6) LN2
    layernorm_kernel<<<NTOK, 256>>>(X1, ln2g, ln2b, Y);

    // 7) H1 = relu(Y @ W1 + b1)  (M=4096, N=3072, K=768)
    {
        dim3 grid(DFF / 128, NTOK / 128, 1);
        gemm_cp<false,true,true,false,true><<<grid, 128, SMEM_NN>>>(Y, W1, b1, nullptr, H1,
            D_MODEL, D_MODEL, DFF, DFF, 0, 1.f, 0,0,0,0,0,0,0,0, 1);
    }

    // 8) W2 split-K=3: partials, then out = P0+P1+P2 + b2 + X1
    {
        dim3 grid(D_MODEL / 128, NTOK / 128, 3);
        gemm_cp<false,false,false,false,false><<<grid, 128, SMEM_NN>>>(H1, W2,
            nullptr, nullptr, P0, DFF/3, DFF, D_MODEL, D_MODEL, 0, 1.f,
            0, (ll)(DFF/3),
            0, (ll)(DFF/3) * D_MODEL,
            0, (ll)NTOK * D_MODEL,
            0, 0, 3);
        const int n4 = NTOK * D_MODEL / 4;
        combine3_kernel<<<(n4 + 255) / 256, 256>>>((const float4*)P0, (const float4*)P1,
                                                   (const float4*)P2, b2,
                                                   (const float4*)X1, (float4*)out, n4);
    }

    (void)in_sizes; (void)n_in; (void)out_size;
}